// round 12
// baseline (speedup 1.0000x reference)
#include <cuda_runtime.h>
#include <cuda_bf16.h>
#include <math.h>
#include <stdint.h>

#define Bz 32
#define Tz 64
#define Sz 128
#define Hz 512
#define Vz 32000
#define Gz 2048   // 4*H
#define NBLK 128
#define NTHR 256

// ---------------- device scratch ----------------
__device__ __align__(16) float d_x[Tz*Bz*Hz];
__device__ __align__(16) float d_g0ih[Tz*Bz*Gz];
__device__ __align__(16) float d_h0buf[2*Bz*Hz];
__device__ __align__(16) float d_h1buf[2*Bz*Hz];
__device__ __align__(16) float d_cstate[2*Bz*Hz];
__device__ __align__(16) float d_cat1[Bz*Hz];
__device__ __align__(16) float d_attq[Bz*Hz];
__device__ float d_bias0[Gz];
__device__ float d_bias1[Gz];
__device__ unsigned d_bar_cnt;
// bf16 hi/lo splits
__device__ __align__(16) __nv_bfloat16 d_Wc_hi[(size_t)Vz*Hz];
__device__ __align__(16) __nv_bfloat16 d_Wc_lo[(size_t)Vz*Hz];
__device__ __align__(16) __nv_bfloat16 d_out_hi[Bz*Tz*Hz];
__device__ __align__(16) __nv_bfloat16 d_out_lo[Bz*Tz*Hz];
__device__ __align__(16) __nv_bfloat16 d_x_hi[Tz*Bz*Hz];
__device__ __align__(16) __nv_bfloat16 d_x_lo[Tz*Bz*Hz];
__device__ __align__(16) __nv_bfloat16 d_Wih0_hi[Gz*Hz];
__device__ __align__(16) __nv_bfloat16 d_Wih0_lo[Gz*Hz];

__device__ __forceinline__ float sigf(float x) { return 1.f / (1.f + expf(-x)); }

// ---------------- packed f32x2 helpers ----------------
__device__ __forceinline__ void ffma2(unsigned long long &d,
                                      unsigned long long a,
                                      unsigned long long b)
{
    asm("fma.rn.f32x2 %0, %1, %2, %0;" : "+l"(d) : "l"(a), "l"(b));
}
__device__ __forceinline__ float2 unpack2(unsigned long long v)
{
    unsigned lo, hi;
    asm("mov.b64 {%0, %1}, %2;" : "=r"(lo), "=r"(hi) : "l"(v));
    return make_float2(__uint_as_float(lo), __uint_as_float(hi));
}

// ---------------- mma.sync / ldmatrix / cp.async helpers ----------------
__device__ __forceinline__ uint32_t smem_u32(const void* p) {
    uint32_t a;
    asm("{ .reg .u64 t; cvta.to.shared.u64 t, %1; cvt.u32.u64 %0, t; }" : "=r"(a) : "l"(p));
    return a;
}
__device__ __forceinline__ void ldsm4(uint32_t (&r)[4], uint32_t addr)
{
    asm volatile("ldmatrix.sync.aligned.m8n8.x4.shared.b16 {%0,%1,%2,%3}, [%4];"
                 : "=r"(r[0]), "=r"(r[1]), "=r"(r[2]), "=r"(r[3]) : "r"(addr));
}
__device__ __forceinline__ void mma_bf16(float (&c)[4], const uint32_t (&a)[4],
                                         const uint32_t* b)
{
    asm volatile(
        "mma.sync.aligned.m16n8k16.row.col.f32.bf16.bf16.f32 "
        "{%0,%1,%2,%3}, {%4,%5,%6,%7}, {%8,%9}, {%0,%1,%2,%3};"
        : "+f"(c[0]), "+f"(c[1]), "+f"(c[2]), "+f"(c[3])
        : "r"(a[0]), "r"(a[1]), "r"(a[2]), "r"(a[3]), "r"(b[0]), "r"(b[1]));
}
#define CP_ASYNC16_CG(dst, src) \
    asm volatile("cp.async.cg.shared.global [%0], [%1], 16;" :: "r"(dst), "l"(src))
#define CP_COMMIT() asm volatile("cp.async.commit_group;" ::: "memory")
#define CP_WAIT(n)  asm volatile("cp.async.wait_group %0;" :: "n"(n) : "memory")

// ---------------- grid barrier ----------------
__device__ __forceinline__ void gbar(unsigned &nbar)
{
    nbar++;
    __syncthreads();
    if (threadIdx.x == 0) {
        __threadfence();
        atomicAdd(&d_bar_cnt, 1u);
        unsigned target = nbar * (unsigned)NBLK;
        while (*(volatile unsigned*)&d_bar_cnt < target) { }
    }
    __syncthreads();
}

// ---------------- fused init ----------------
__global__ void init_kernel(const int* __restrict__ ids32, const float* __restrict__ emb,
                            const float* __restrict__ bih, const float* __restrict__ bhh,
                            const float* __restrict__ h0, const float* __restrict__ c0)
{
    int i = blockIdx.x * blockDim.x + threadIdx.x;
    if (i == 0) d_bar_cnt = 0u;
    if (i < Gz) {
        d_bias0[i] = bih[i] + bhh[i];
        d_bias1[i] = bih[Gz + i] + bhh[Gz + i];
    }
    if (i < Bz*Hz) {
        d_h0buf[i] = h0[i];
        d_h1buf[i] = h0[Bz*Hz + i];
    }
    if (i < 2*Bz*Hz) d_cstate[i] = c0[i];
    if (i < Tz*Bz*Hz) {
        bool is64 = (ids32[1] == 0) && (ids32[3] == 0) && (ids32[5] == 0);
        int h = i % Hz;
        int tb = i / Hz;
        int b = tb % Bz;
        int t = tb / Bz;
        int idx = b*Tz + t;
        int id = is64 ? ids32[2*idx] : ids32[idx];
        if (id < 0 || id >= Vz) id = 0;
        float v = (id == 0) ? 0.f : emb[(size_t)id*Hz + h];
        d_x[i] = v;
        __nv_bfloat16 hv = __float2bfloat16(v);
        d_x_hi[i] = hv;
        d_x_lo[i] = __float2bfloat16(v - __bfloat162float(hv));
    }
}

// ---------------- hi/lo bf16 split (vectorized) ----------------
__global__ void split_kernel(const float4* __restrict__ src,
                             uint2* __restrict__ hi,
                             uint2* __restrict__ lo, size_t n4)
{
    size_t i = (size_t)blockIdx.x * blockDim.x + threadIdx.x;
    if (i >= n4) return;
    float4 v = src[i];
    __nv_bfloat16 hx = __float2bfloat16(v.x);
    __nv_bfloat16 hy = __float2bfloat16(v.y);
    __nv_bfloat16 hz = __float2bfloat16(v.z);
    __nv_bfloat16 hw = __float2bfloat16(v.w);
    __nv_bfloat16 lx = __float2bfloat16(v.x - __bfloat162float(hx));
    __nv_bfloat16 ly = __float2bfloat16(v.y - __bfloat162float(hy));
    __nv_bfloat16 lz = __float2bfloat16(v.z - __bfloat162float(hz));
    __nv_bfloat16 lw = __float2bfloat16(v.w - __bfloat162float(hw));
    uint2 ho, lu;
    ho.x = (uint32_t)__bfloat16_as_ushort(hx) | ((uint32_t)__bfloat16_as_ushort(hy) << 16);
    ho.y = (uint32_t)__bfloat16_as_ushort(hz) | ((uint32_t)__bfloat16_as_ushort(hw) << 16);
    lu.x = (uint32_t)__bfloat16_as_ushort(lx) | ((uint32_t)__bfloat16_as_ushort(ly) << 16);
    lu.y = (uint32_t)__bfloat16_as_ushort(lz) | ((uint32_t)__bfloat16_as_ushort(lw) << 16);
    hi[i] = ho;
    lo[i] = lu;
}

// ---------------- bf16-split mma GEMM: C[M,N] = A @ B^T + bias ---------------
// 128x128 CTA tile, 4 warps (2m x 2n), warp tile 64x64 (2x fragment reuse).
// 3 products Ah*Bh + Al*Bh + Ah*Bl, fp32 accum; cp.async double-buffered.
#define KC    32
#define KCP   40
#define ARRB  (128*KCP*2)                // 10240
#define BUFB  (4*ARRB)                   // 40960

__global__ void __launch_bounds__(128, 2)
mma_gemm_kernel(const __nv_bfloat16* __restrict__ Ahi, const __nv_bfloat16* __restrict__ Alo,
                const __nv_bfloat16* __restrict__ Bhi, const __nv_bfloat16* __restrict__ Blo,
                const float* __restrict__ bias, float* __restrict__ C, int ldc)
{
    extern __shared__ __align__(16) char sm_raw[];

    const int tid  = threadIdx.x;
    const int lane = tid & 31;
    const int wid  = tid >> 5;     // 0..3
    const int wm   = wid >> 1;     // 0..1 (64 rows)
    const int wn   = wid & 1;      // 0..1 (64 cols)
    const int n0   = blockIdx.x * 128;
    const int m0   = blockIdx.y * 128;

    float acc[4][8][4];
#pragma unroll
    for (int i = 0; i < 4; ++i)
#pragma unroll
        for (int j = 0; j < 8; ++j)
#pragma unroll
            for (int v = 0; v < 4; ++v) acc[i][j][v] = 0.f;

    const uint32_t smBase = smem_u32(sm_raw);

    // staging: 1 row per thread, 4 x 16B per array (KC=32 halves = 64B/row)
    auto stage = [&](int c, int buf) {
        const int k0 = c * KC;
        uint32_t db = smBase + buf*BUFB + tid*(KCP*2);
        const __nv_bfloat16* pAh = Ahi + (size_t)(m0 + tid)*Hz + k0;
        const __nv_bfloat16* pAl = Alo + (size_t)(m0 + tid)*Hz + k0;
        const __nv_bfloat16* pBh = Bhi + (size_t)(n0 + tid)*Hz + k0;
        const __nv_bfloat16* pBl = Blo + (size_t)(n0 + tid)*Hz + k0;
#pragma unroll
        for (int i = 0; i < 4; ++i) {
            CP_ASYNC16_CG(db + i*16 + 0*ARRB, pAh + i*8);
            CP_ASYNC16_CG(db + i*16 + 1*ARRB, pAl + i*8);
            CP_ASYNC16_CG(db + i*16 + 2*ARRB, pBh + i*8);
            CP_ASYNC16_CG(db + i*16 + 3*ARRB, pBl + i*8);
        }
        CP_COMMIT();
    };

    const int NCHUNK = Hz / KC;   // 16
    stage(0, 0);

    for (int c = 0; c < NCHUNK; ++c) {
        if (c + 1 < NCHUNK) { stage(c + 1, (c + 1) & 1); CP_WAIT(1); }
        else                { CP_WAIT(0); }
        __syncthreads();

        const uint32_t bb  = smBase + (c & 1)*BUFB;
        const uint32_t uAh = bb;
        const uint32_t uAl = bb + 1*ARRB;
        const uint32_t uBh = bb + 2*ARRB;
        const uint32_t uBl = bb + 3*ARRB;

#pragma unroll
        for (int ks = 0; ks < KC/16; ++ks) {
            const int arow = wm*64 + (lane & 15);
            const int acol = ks*16 + ((lane >> 4) << 3);
            const int brow = wn*64 + (lane & 7) + ((lane >> 4) << 3);
            const int bcol = ks*16 + (lane & 8);

            uint32_t fA[4][4], fX[4][4], fB[8][2];

            // A-hi fragments (resident for passes 1 and 3)
#pragma unroll
            for (int mt = 0; mt < 4; ++mt)
                ldsm4(fA[mt], uAh + ((arow + mt*16)*KCP + acol) * 2);
            // B-hi fragments
#pragma unroll
            for (int p = 0; p < 4; ++p) {
                uint32_t t4[4];
                ldsm4(t4, uBh + ((brow + p*16)*KCP + bcol) * 2);
                fB[2*p][0] = t4[0]; fB[2*p][1] = t4[1];
                fB[2*p+1][0] = t4[2]; fB[2*p+1][1] = t4[3];
            }
            // pass 1: Ah * Bh
#pragma unroll
            for (int mt = 0; mt < 4; ++mt)
#pragma unroll
                for (int nt = 0; nt < 8; ++nt) mma_bf16(acc[mt][nt], fA[mt], fB[nt]);
            // A-lo fragments; pass 2: Al * Bh (Bh still resident)
#pragma unroll
            for (int mt = 0; mt < 4; ++mt)
                ldsm4(fX[mt], uAl + ((arow + mt*16)*KCP + acol) * 2);
#pragma unroll
            for (int mt = 0; mt < 4; ++mt)
#pragma unroll
                for (int nt = 0; nt < 8; ++nt) mma_bf16(acc[mt][nt], fX[mt], fB[nt]);
            // B-lo fragments (overwrite fB); pass 3: Ah * Bl
#pragma unroll
            for (int p = 0; p < 4; ++p) {
                uint32_t t4[4];
                ldsm4(t4, uBl + ((brow + p*16)*KCP + bcol) * 2);
                fB[2*p][0] = t4[0]; fB[2*p][1] = t4[1];
                fB[2*p+1][0] = t4[2]; fB[2*p+1][1] = t4[3];
            }
#pragma unroll
            for (int mt = 0; mt < 4; ++mt)
#pragma unroll
                for (int nt = 0; nt < 8; ++nt) mma_bf16(acc[mt][nt], fA[mt], fB[nt]);
        }
        __syncthreads();
    }

    const int gid = lane >> 2;
    const int tig = lane & 3;
#pragma unroll
    for (int mt = 0; mt < 4; ++mt) {
        int mA = m0 + wm*64 + mt*16 + gid;
#pragma unroll
        for (int nt = 0; nt < 8; ++nt) {
            int n = n0 + wn*64 + nt*8 + tig*2;
            float2 bv = *(const float2*)&bias[n];
            float2 v0 = make_float2(acc[mt][nt][0] + bv.x, acc[mt][nt][1] + bv.y);
            float2 v1 = make_float2(acc[mt][nt][2] + bv.x, acc[mt][nt][3] + bv.y);
            *(float2*)&C[(size_t)mA*ldc + n]     = v0;
            *(float2*)&C[(size_t)(mA+8)*ldc + n] = v1;
        }
    }
}

// ---------------- persistent scan (unchanged from round 11) ----------------
#define SC_HB     0
#define SC_SG     65536
#define SC_ATTQ   (SC_SG + 32768)
#define SC_SC     (SC_ATTQ + 2048)
#define SC_LSE    (SC_SC + 512)
#define SC_TOTAL  (SC_LSE + 16)

__global__ void __launch_bounds__(NTHR, 1)
scan_kernel(const float* __restrict__ ctx, const float* __restrict__ Whh,
            const float* __restrict__ Wih)
{
    extern __shared__ __align__(16) char dynsm[];
    float*  sgp    = (float*)(dynsm + SC_SG);
    float*  attq_s = (float*)(dynsm + SC_ATTQ);
    float*  sc_s   = (float*)(dynsm + SC_SC);
    float*  s_lse  = (float*)(dynsm + SC_LSE);
    const uint32_t smHb = smem_u32(dynsm);

    const int tid  = threadIdx.x;
    const int lane = tid & 31;
    const int w    = tid >> 5;
    const int blk  = blockIdx.x;
    const int j0   = blk * 4;
    const bool att_on = (blk & 1) == 0;
    const int cb   = blk >> 2;
    const int chalf = (blk >> 1) & 1;

    const int lr0 = 2*w, lr1 = 2*w + 1;
    const int n0 = (lr0 >> 2)*Hz + j0 + (lr0 & 3);
    const int n1 = (lr1 >> 2)*Hz + j0 + (lr1 & 3);

    ulonglong2 wA0[4], wA1[4], wB0[8], wB1[8];
    {
        const ulonglong2* W0 = (const ulonglong2*)(Whh + (size_t)n0*Hz);
        const ulonglong2* W1 = (const ulonglong2*)(Whh + (size_t)n1*Hz);
#pragma unroll
        for (int i = 0; i < 4; ++i) { wA0[i] = W0[lane + 32*i]; wA1[i] = W1[lane + 32*i]; }
        const ulonglong2* I0 = (const ulonglong2*)(Wih + (size_t)(Gz + n0)*Hz);
        const ulonglong2* I1 = (const ulonglong2*)(Wih + (size_t)(Gz + n1)*Hz);
        const ulonglong2* H0 = (const ulonglong2*)(Whh + (size_t)(Gz + n0)*Hz);
        const ulonglong2* H1 = (const ulonglong2*)(Whh + (size_t)(Gz + n1)*Hz);
#pragma unroll
        for (int i = 0; i < 4; ++i) {
            wB0[i]   = I0[lane + 32*i];  wB1[i]   = I1[lane + 32*i];
            wB0[4+i] = H0[lane + 32*i];  wB1[4+i] = H1[lane + 32*i];
        }
    }

    auto stageH = [&](const float4* src, int buf) {
        uint32_t db = smHb + buf*32768 + tid*16;
#pragma unroll
        for (int i = 0; i < 8; ++i)
            CP_ASYNC16_CG(db + i*NTHR*16, src + tid + i*NTHR);
        CP_COMMIT();
    };

    auto gates16 = [&](int buf, int boff, int slotbase,
                       const ulonglong2* wr0, const ulonglong2* wr1) {
        const ulonglong2* hb2 = (const ulonglong2*)(dynsm + buf*32768);
#pragma unroll 2
        for (int bl = 0; bl < 16; ++bl) {
            unsigned long long a0 = 0ull, a1 = 0ull;
            const ulonglong2* hr = hb2 + bl*128;
#pragma unroll
            for (int i = 0; i < 4; ++i) {
                ulonglong2 h2 = hr[lane + 32*i];
                ffma2(a0, h2.x, wr0[i].x); ffma2(a0, h2.y, wr0[i].y);
                ffma2(a1, h2.x, wr1[i].x); ffma2(a1, h2.y, wr1[i].y);
            }
            float2 f0 = unpack2(a0), f1 = unpack2(a1);
            float s0 = f0.x + f0.y, s1 = f1.x + f1.y;
            s0 += __shfl_xor_sync(0xffffffffu, s0, 16);
            s1 += __shfl_xor_sync(0xffffffffu, s1, 16);
            s0 += __shfl_xor_sync(0xffffffffu, s0, 8);
            s1 += __shfl_xor_sync(0xffffffffu, s1, 8);
            if (lane < 8) {
                int b = boff + bl;
                sgp[(lr0*32 + b)*16 + slotbase + lane] = s0;
                sgp[(lr1*32 + b)*16 + slotbase + lane] = s1;
            }
        }
    };

    unsigned nbar = 0;

    for (int t = 0; t < Tz; ++t) {
        const int p = t & 1;
        const float* h0p = d_h0buf + p*Bz*Hz;
        float*       h0n = d_h0buf + (p^1)*Bz*Hz;
        const float* h1p = d_h1buf + p*Bz*Hz;
        float*       h1n = d_h1buf + (p^1)*Bz*Hz;

        // ===== Phase A =====
        {
            const float4* Hp = (const float4*)h0p;
            stageH(Hp, 0);
            stageH(Hp + 2048, 1);
            CP_WAIT(1); __syncthreads();
            gates16(0, 0, 0, wA0, wA1);
            CP_WAIT(0); __syncthreads();
            gates16(1, 16, 0, wA0, wA1);
            __syncthreads();
            if (tid < 128) {
                int b = tid >> 2, jj = tid & 3;
                int j = j0 + jj;
                const float* seed = d_g0ih + ((size_t)t*Bz + b)*Gz;
                float g4[4];
#pragma unroll
                for (int g = 0; g < 4; ++g) {
                    const float4* q = (const float4*)&sgp[((g*4 + jj)*32 + b)*16];
                    float4 q0 = q[0], q1 = q[1];
                    g4[g] = (q0.x + q0.y) + (q0.z + q0.w) + (q1.x + q1.y) + (q1.z + q1.w);
                }
                float gi = g4[0] + seed[j];
                float gf = g4[1] + seed[Hz + j];
                float gg = g4[2] + seed[2*Hz + j];
                float go = g4[3] + seed[3*Hz + j];
                int ci = b*Hz + j;
                float c = sigf(gf)*d_cstate[ci] + sigf(gi)*tanhf(gg);
                float h = sigf(go)*tanhf(c);
                d_cstate[ci] = c;
                __stcg(&h0n[ci], h);
                __stcg(&d_cat1[ci], h + d_x[((size_t)t*Bz + b)*Hz + j]);
            }
        }
        gbar(nbar);

        // ===== Phase B =====
        {
            const float4* srcs[4] = { (const float4*)d_cat1, (const float4*)d_cat1 + 2048,
                                      (const float4*)h1p,    (const float4*)h1p + 2048 };
            stageH(srcs[0], 0);
            stageH(srcs[1], 1);
#pragma unroll
            for (int r = 0; r < 4; ++r) {
                CP_WAIT(1); __syncthreads();
                const ulonglong2* wr0 = (r < 2) ? wB0 : (wB0 + 4);
                const ulonglong2* wr1 = (r < 2) ? wB1 : (wB1 + 4);
                gates16(r & 1, (r & 1)*16, (r < 2) ? 0 : 8, wr0, wr1);
                __syncthreads();
                if (r + 2 < 4) stageH(srcs[r + 2], r & 1);
                if (r == 2) { CP_WAIT(0); }
            }
            __syncthreads();
            if (tid < 128) {
                int b = tid >> 2, jj = tid & 3;
                int j = j0 + jj;
                float g4[4];
#pragma unroll
                for (int g = 0; g < 4; ++g) {
                    const float4* q = (const float4*)&sgp[((g*4 + jj)*32 + b)*16];
                    float4 q0 = q[0], q1 = q[1], q2 = q[2], q3 = q[3];
                    g4[g] = ((q0.x + q0.y) + (q0.z + q0.w)) + ((q1.x + q1.y) + (q1.z + q1.w))
                          + ((q2.x + q2.y) + (q2.z + q2.w)) + ((q3.x + q3.y) + (q3.z + q3.w));
                }
                float gi = g4[0] + d_bias1[j];
                float gf = g4[1] + d_bias1[Hz + j];
                float gg = g4[2] + d_bias1[2*Hz + j];
                float go = g4[3] + d_bias1[3*Hz + j];
                int ci = Bz*Hz + b*Hz + j;
                float c = sigf(gf)*d_cstate[ci] + sigf(gi)*tanhf(gg);
                float h = sigf(go)*tanhf(c);
                d_cstate[ci] = c;
                __stcg(&h1n[b*Hz + j], h);
                __stcg(&d_attq[b*Hz + j], h + __ldcg(&d_cat1[b*Hz + j]));
            }
        }
        gbar(nbar);

        // ===== Phase C (even blocks; batch cb, H-half chalf) =====
        if (att_on) {
            for (int i = tid; i < Hz; i += NTHR) attq_s[i] = __ldcg(&d_attq[cb*Hz + i]);
            __syncthreads();

            const float4* A4 = (const float4*)attq_s;
            for (int s = w*16; s < w*16 + 16; ++s) {
                const float4* C4 = (const float4*)(ctx + ((size_t)cb*Sz + s)*Hz);
                float acc = 0.f;
#pragma unroll
                for (int i = 0; i < 4; ++i) {
                    float4 c4 = C4[lane + 32*i];
                    float4 a4 = A4[lane + 32*i];
                    acc += c4.x*a4.x + c4.y*a4.y + c4.z*a4.z + c4.w*a4.w;
                }
#pragma unroll
                for (int o = 16; o; o >>= 1) acc += __shfl_xor_sync(0xffffffffu, acc, o);
                if (lane == 0) sc_s[s] = acc;
            }
            __syncthreads();

            if (w == 0) {
                float m = -1e30f;
                for (int s = lane; s < Sz; s += 32) m = fmaxf(m, sc_s[s]);
#pragma unroll
                for (int o = 16; o; o >>= 1) m = fmaxf(m, __shfl_xor_sync(0xffffffffu, m, o));
                float sm = 0.f;
                for (int s = lane; s < Sz; s += 32) sm += expf(sc_s[s] - m);
#pragma unroll
                for (int o = 16; o; o >>= 1) sm += __shfl_xor_sync(0xffffffffu, sm, o);
                if (lane == 0) *s_lse = m + logf(sm);
            }
            __syncthreads();
            float lse = *s_lse;

            int h = chalf*256 + tid;
            const float* cp = ctx + (size_t)cb*Sz*Hz + h;
            float acc = 0.f;
#pragma unroll 8
            for (int s = 0; s < Sz; ++s)
                acc += cp[(size_t)s*Hz] * (sc_s[s] - lse);
            size_t oi = ((size_t)cb*Tz + t)*Hz + h;
            __nv_bfloat16 hv = __float2bfloat16(acc);
            d_out_hi[oi] = hv;
            d_out_lo[oi] = __float2bfloat16(acc - __bfloat162float(hv));
            __syncthreads();
        }
    }
}

// ---------------- tail: hT, cT ----------------
__global__ void tail_kernel(float* __restrict__ out)
{
    int i = blockIdx.x * blockDim.x + threadIdx.x;
    const size_t base = (size_t)Bz*Tz*Vz;
    if (i < Bz*Hz)                 out[base + i] = d_h0buf[i];
    else if (i < 2*Bz*Hz)          out[base + i] = d_h1buf[i - Bz*Hz];
    else if (i < 4*Bz*Hz)          out[base + i] = d_cstate[i - 2*Bz*Hz];
}

// ---------------- launch ----------------
extern "C" void kernel_launch(void* const* d_in, const int* in_sizes, int n_in,
                              void* d_out, int out_size)
{
    const float* context = (const float*)d_in[0];
    const int*   dec     = (const int*)d_in[1];
    const float* h0      = (const float*)d_in[2];
    const float* c0      = (const float*)d_in[3];
    const float* emb     = (const float*)d_in[4];
    const float* Wih     = (const float*)d_in[5];
    const float* Whh     = (const float*)d_in[6];
    const float* bih     = (const float*)d_in[7];
    const float* bhh     = (const float*)d_in[8];
    const float* Wc      = (const float*)d_in[9];
    const float* bc      = (const float*)d_in[10];
    float* out = (float*)d_out;

    float *p_g0ih, *p_b0;
    __nv_bfloat16 *p_wch, *p_wcl, *p_oh, *p_ol, *p_xh, *p_xl, *p_wih, *p_wil;
    cudaGetSymbolAddress((void**)&p_g0ih, d_g0ih);
    cudaGetSymbolAddress((void**)&p_b0,   d_bias0);
    cudaGetSymbolAddress((void**)&p_wch,  d_Wc_hi);
    cudaGetSymbolAddress((void**)&p_wcl,  d_Wc_lo);
    cudaGetSymbolAddress((void**)&p_oh,   d_out_hi);
    cudaGetSymbolAddress((void**)&p_ol,   d_out_lo);
    cudaGetSymbolAddress((void**)&p_xh,   d_x_hi);
    cudaGetSymbolAddress((void**)&p_xl,   d_x_lo);
    cudaGetSymbolAddress((void**)&p_wih,  d_Wih0_hi);
    cudaGetSymbolAddress((void**)&p_wil,  d_Wih0_lo);

    const int SMEM_MMA = 2 * BUFB;   // 81920 -> 2 CTAs/SM
    cudaFuncSetAttribute(mma_gemm_kernel,
                         cudaFuncAttributeMaxDynamicSharedMemorySize, SMEM_MMA);
    cudaFuncSetAttribute(scan_kernel,
                         cudaFuncAttributeMaxDynamicSharedMemorySize, SC_TOTAL);

    init_kernel<<<(Tz*Bz*Hz + 255)/256, 256>>>(dec, emb, bih, bhh, h0, c0);

    {
        size_t n4 = (size_t)Vz*Hz/4;
        split_kernel<<<(unsigned)((n4 + 255)/256), 256>>>((const float4*)Wc, (uint2*)p_wch, (uint2*)p_wcl, n4);
        size_t m4 = (size_t)Gz*Hz/4;
        split_kernel<<<(unsigned)((m4 + 255)/256), 256>>>((const float4*)Wih, (uint2*)p_wih, (uint2*)p_wil, m4);
    }

    // g0ih = x @ Wih0^T + bias0
    {
        dim3 grid(Gz/128, (Tz*Bz)/128);
        mma_gemm_kernel<<<grid, 128, SMEM_MMA>>>(p_xh, p_xl, p_wih, p_wil, p_b0, p_g0ih, Gz);
    }

    // persistent scan
    scan_kernel<<<NBLK, NTHR, SC_TOTAL>>>(context, Whh, Wih);

    // logits = outs @ Wc^T + bc
    {
        dim3 grid(Vz/128, (Bz*Tz)/128);
        mma_gemm_kernel<<<grid, 128, SMEM_MMA>>>(p_oh, p_ol, p_wch, p_wcl, bc, out, Vz);
    }

    if ((long long)out_size >= (long long)Bz*Tz*Vz + 4LL*Bz*Hz) {
        tail_kernel<<<(4*Bz*Hz + 255)/256, 256>>>(out);
    }
}

// round 13
// speedup vs baseline: 1.0638x; 1.0638x over previous
#include <cuda_runtime.h>
#include <cuda_bf16.h>
#include <math.h>
#include <stdint.h>

#define Bz 32
#define Tz 64
#define Sz 128
#define Hz 512
#define Vz 32000
#define Gz 2048   // 4*H
#define NBLK 128
#define NTHR 256

// ---------------- device scratch ----------------
__device__ __align__(16) float d_x[Tz*Bz*Hz];
__device__ __align__(16) float d_g0ih[Tz*Bz*Gz];
__device__ __align__(16) float d_h0buf[2*Bz*Hz];
__device__ __align__(16) float d_h1buf[2*Bz*Hz];
__device__ __align__(16) float d_cstate[2*Bz*Hz];
__device__ __align__(16) float d_cat1[Bz*Hz];
__device__ __align__(16) float d_attq[Bz*Hz];
__device__ float d_bias0[Gz];
__device__ float d_bias1[Gz];
__device__ __align__(128) unsigned d_bar_cnt8[8*32];   // 8 counters, 128B apart
// bf16 hi/lo splits
__device__ __align__(16) __nv_bfloat16 d_Wc_hi[(size_t)Vz*Hz];
__device__ __align__(16) __nv_bfloat16 d_Wc_lo[(size_t)Vz*Hz];
__device__ __align__(16) __nv_bfloat16 d_out_hi[Bz*Tz*Hz];
__device__ __align__(16) __nv_bfloat16 d_out_lo[Bz*Tz*Hz];
__device__ __align__(16) __nv_bfloat16 d_x_hi[Tz*Bz*Hz];
__device__ __align__(16) __nv_bfloat16 d_x_lo[Tz*Bz*Hz];
__device__ __align__(16) __nv_bfloat16 d_Wih0_hi[Gz*Hz];
__device__ __align__(16) __nv_bfloat16 d_Wih0_lo[Gz*Hz];

__device__ __forceinline__ float sigf(float x) { return 1.f / (1.f + expf(-x)); }

// ---------------- packed f32x2 helpers ----------------
__device__ __forceinline__ void ffma2(unsigned long long &d,
                                      unsigned long long a,
                                      unsigned long long b)
{
    asm("fma.rn.f32x2 %0, %1, %2, %0;" : "+l"(d) : "l"(a), "l"(b));
}
__device__ __forceinline__ float2 unpack2(unsigned long long v)
{
    unsigned lo, hi;
    asm("mov.b64 {%0, %1}, %2;" : "=r"(lo), "=r"(hi) : "l"(v));
    return make_float2(__uint_as_float(lo), __uint_as_float(hi));
}

// ---------------- mma.sync / ldmatrix / cp.async helpers ----------------
__device__ __forceinline__ uint32_t smem_u32(const void* p) {
    uint32_t a;
    asm("{ .reg .u64 t; cvta.to.shared.u64 t, %1; cvt.u32.u64 %0, t; }" : "=r"(a) : "l"(p));
    return a;
}
__device__ __forceinline__ void ldsm4(uint32_t (&r)[4], uint32_t addr)
{
    asm volatile("ldmatrix.sync.aligned.m8n8.x4.shared.b16 {%0,%1,%2,%3}, [%4];"
                 : "=r"(r[0]), "=r"(r[1]), "=r"(r[2]), "=r"(r[3]) : "r"(addr));
}
__device__ __forceinline__ void mma_bf16(float (&c)[4], const uint32_t (&a)[4],
                                         const uint32_t* b)
{
    asm volatile(
        "mma.sync.aligned.m16n8k16.row.col.f32.bf16.bf16.f32 "
        "{%0,%1,%2,%3}, {%4,%5,%6,%7}, {%8,%9}, {%0,%1,%2,%3};"
        : "+f"(c[0]), "+f"(c[1]), "+f"(c[2]), "+f"(c[3])
        : "r"(a[0]), "r"(a[1]), "r"(a[2]), "r"(a[3]), "r"(b[0]), "r"(b[1]));
}
#define CP_ASYNC16_CG(dst, src) \
    asm volatile("cp.async.cg.shared.global [%0], [%1], 16;" :: "r"(dst), "l"(src))
#define CP_COMMIT() asm volatile("cp.async.commit_group;" ::: "memory")
#define CP_WAIT(n)  asm volatile("cp.async.wait_group %0;" :: "n"(n) : "memory")

// ---------------- grid barrier: 8 distributed counters ----------------
__device__ __forceinline__ void gbar(unsigned &nbar, int blk)
{
    nbar++;
    __syncthreads();
    if (threadIdx.x == 0) {
        __threadfence();
        atomicAdd(&d_bar_cnt8[(blk & 7) * 32], 1u);
        const unsigned target = nbar * (NBLK / 8);
        for (;;) {
            bool done = true;
#pragma unroll
            for (int i = 0; i < 8; ++i)
                done &= (*(volatile unsigned*)&d_bar_cnt8[i * 32] >= target);
            if (done) break;
        }
    }
    __syncthreads();
}

// ---------------- fused init ----------------
__global__ void init_kernel(const int* __restrict__ ids32, const float* __restrict__ emb,
                            const float* __restrict__ bih, const float* __restrict__ bhh,
                            const float* __restrict__ h0, const float* __restrict__ c0)
{
    int i = blockIdx.x * blockDim.x + threadIdx.x;
    if (i < 8) d_bar_cnt8[i * 32] = 0u;
    if (i < Gz) {
        d_bias0[i] = bih[i] + bhh[i];
        d_bias1[i] = bih[Gz + i] + bhh[Gz + i];
    }
    if (i < Bz*Hz) {
        d_h0buf[i] = h0[i];
        d_h1buf[i] = h0[Bz*Hz + i];
    }
    if (i < 2*Bz*Hz) d_cstate[i] = c0[i];
    if (i < Tz*Bz*Hz) {
        bool is64 = (ids32[1] == 0) && (ids32[3] == 0) && (ids32[5] == 0);
        int h = i % Hz;
        int tb = i / Hz;
        int b = tb % Bz;
        int t = tb / Bz;
        int idx = b*Tz + t;
        int id = is64 ? ids32[2*idx] : ids32[idx];
        if (id < 0 || id >= Vz) id = 0;
        float v = (id == 0) ? 0.f : emb[(size_t)id*Hz + h];
        d_x[i] = v;
        __nv_bfloat16 hv = __float2bfloat16(v);
        d_x_hi[i] = hv;
        d_x_lo[i] = __float2bfloat16(v - __bfloat162float(hv));
    }
}

// ---------------- hi/lo bf16 split (vectorized) ----------------
__global__ void split_kernel(const float4* __restrict__ src,
                             uint2* __restrict__ hi,
                             uint2* __restrict__ lo, size_t n4)
{
    size_t i = (size_t)blockIdx.x * blockDim.x + threadIdx.x;
    if (i >= n4) return;
    float4 v = src[i];
    __nv_bfloat16 hx = __float2bfloat16(v.x);
    __nv_bfloat16 hy = __float2bfloat16(v.y);
    __nv_bfloat16 hz = __float2bfloat16(v.z);
    __nv_bfloat16 hw = __float2bfloat16(v.w);
    __nv_bfloat16 lx = __float2bfloat16(v.x - __bfloat162float(hx));
    __nv_bfloat16 ly = __float2bfloat16(v.y - __bfloat162float(hy));
    __nv_bfloat16 lz = __float2bfloat16(v.z - __bfloat162float(hz));
    __nv_bfloat16 lw = __float2bfloat16(v.w - __bfloat162float(hw));
    uint2 ho, lu;
    ho.x = (uint32_t)__bfloat16_as_ushort(hx) | ((uint32_t)__bfloat16_as_ushort(hy) << 16);
    ho.y = (uint32_t)__bfloat16_as_ushort(hz) | ((uint32_t)__bfloat16_as_ushort(hw) << 16);
    lu.x = (uint32_t)__bfloat16_as_ushort(lx) | ((uint32_t)__bfloat16_as_ushort(ly) << 16);
    lu.y = (uint32_t)__bfloat16_as_ushort(lz) | ((uint32_t)__bfloat16_as_ushort(lw) << 16);
    hi[i] = ho;
    lo[i] = lu;
}

// ---------------- bf16-split mma GEMM (round-11 config: 8 warps, 64x32 tile) --
#define KC    32
#define KCP   40
#define ARRB  (128*KCP*2)                // 10240
#define BUFB  (4*ARRB)                   // 40960

__global__ void __launch_bounds__(256, 2)
mma_gemm_kernel(const __nv_bfloat16* __restrict__ Ahi, const __nv_bfloat16* __restrict__ Alo,
                const __nv_bfloat16* __restrict__ Bhi, const __nv_bfloat16* __restrict__ Blo,
                const float* __restrict__ bias, float* __restrict__ C, int ldc)
{
    extern __shared__ __align__(16) char sm_raw[];

    const int tid  = threadIdx.x;
    const int lane = tid & 31;
    const int wid  = tid >> 5;
    const int wm   = wid >> 2;
    const int wn   = wid & 3;
    const int n0   = blockIdx.x * 128;
    const int m0   = blockIdx.y * 128;

    float acc[4][4][4];
#pragma unroll
    for (int i = 0; i < 4; ++i)
#pragma unroll
        for (int j = 0; j < 4; ++j)
#pragma unroll
            for (int v = 0; v < 4; ++v) acc[i][j][v] = 0.f;

    const int gr = tid >> 1;
    const int gs = (tid & 1) * 2;

    const uint32_t smBase = smem_u32(sm_raw);

    auto stage = [&](int c, int buf) {
        const int k0 = c * KC;
        uint32_t db = smBase + buf*BUFB + gr*(KCP*2) + gs*16;
        const __nv_bfloat16* pAh = Ahi + (size_t)(m0 + gr)*Hz + k0 + gs*8;
        const __nv_bfloat16* pAl = Alo + (size_t)(m0 + gr)*Hz + k0 + gs*8;
        const __nv_bfloat16* pBh = Bhi + (size_t)(n0 + gr)*Hz + k0 + gs*8;
        const __nv_bfloat16* pBl = Blo + (size_t)(n0 + gr)*Hz + k0 + gs*8;
#pragma unroll
        for (int i = 0; i < 2; ++i) {
            CP_ASYNC16_CG(db + i*16 + 0*ARRB, pAh + i*8);
            CP_ASYNC16_CG(db + i*16 + 1*ARRB, pAl + i*8);
            CP_ASYNC16_CG(db + i*16 + 2*ARRB, pBh + i*8);
            CP_ASYNC16_CG(db + i*16 + 3*ARRB, pBl + i*8);
        }
        CP_COMMIT();
    };

    const int NCHUNK = Hz / KC;   // 16
    stage(0, 0);

    for (int c = 0; c < NCHUNK; ++c) {
        if (c + 1 < NCHUNK) { stage(c + 1, (c + 1) & 1); CP_WAIT(1); }
        else                { CP_WAIT(0); }
        __syncthreads();

        const uint32_t bb  = smBase + (c & 1)*BUFB;
        const uint32_t uAh = bb;
        const uint32_t uAl = bb + 1*ARRB;
        const uint32_t uBh = bb + 2*ARRB;
        const uint32_t uBl = bb + 3*ARRB;

#pragma unroll
        for (int ks = 0; ks < KC/16; ++ks) {
            uint32_t fAh[4][4], fAl[4][4], fBh[4][2], fBl[4][2];
            const int arow = wm*64 + (lane & 15);
            const int acol = ks*16 + ((lane >> 4) << 3);
#pragma unroll
            for (int mt = 0; mt < 4; ++mt) {
                uint32_t off = ((arow + mt*16)*KCP + acol) * 2;
                ldsm4(fAh[mt], uAh + off);
                ldsm4(fAl[mt], uAl + off);
            }
            const int brow = wn*32 + (lane & 7) + ((lane >> 4) << 3);
            const int bcol = ks*16 + (lane & 8);
#pragma unroll
            for (int p = 0; p < 2; ++p) {
                uint32_t off = ((brow + p*16)*KCP + bcol) * 2;
                uint32_t t4[4];
                ldsm4(t4, uBh + off);
                fBh[2*p][0] = t4[0]; fBh[2*p][1] = t4[1];
                fBh[2*p+1][0] = t4[2]; fBh[2*p+1][1] = t4[3];
                ldsm4(t4, uBl + off);
                fBl[2*p][0] = t4[0]; fBl[2*p][1] = t4[1];
                fBl[2*p+1][0] = t4[2]; fBl[2*p+1][1] = t4[3];
            }
#pragma unroll
            for (int mt = 0; mt < 4; ++mt)
#pragma unroll
                for (int nt = 0; nt < 4; ++nt) mma_bf16(acc[mt][nt], fAh[mt], fBh[nt]);
#pragma unroll
            for (int mt = 0; mt < 4; ++mt)
#pragma unroll
                for (int nt = 0; nt < 4; ++nt) mma_bf16(acc[mt][nt], fAh[mt], fBl[nt]);
#pragma unroll
            for (int mt = 0; mt < 4; ++mt)
#pragma unroll
                for (int nt = 0; nt < 4; ++nt) mma_bf16(acc[mt][nt], fAl[mt], fBh[nt]);
        }
        __syncthreads();
    }

    const int gid = lane >> 2;
    const int tig = lane & 3;
#pragma unroll
    for (int mt = 0; mt < 4; ++mt) {
        int mA = m0 + wm*64 + mt*16 + gid;
#pragma unroll
        for (int nt = 0; nt < 4; ++nt) {
            int n = n0 + wn*32 + nt*8 + tig*2;
            float2 bv = *(const float2*)&bias[n];
            float2 v0 = make_float2(acc[mt][nt][0] + bv.x, acc[mt][nt][1] + bv.y);
            float2 v1 = make_float2(acc[mt][nt][2] + bv.x, acc[mt][nt][3] + bv.y);
            *(float2*)&C[(size_t)mA*ldc + n]     = v0;
            *(float2*)&C[(size_t)(mA+8)*ldc + n] = v1;
        }
    }
}

// ---------------- persistent scan ----------------
#define SC_HB     0
#define SC_SG     65536
#define SC_ATTQ   (SC_SG + 32768)
#define SC_SC     (SC_ATTQ + 2048)
#define SC_LSE    (SC_SC + 512)
#define SC_TOTAL  (SC_LSE + 16)

__global__ void __launch_bounds__(NTHR, 1)
scan_kernel(const float* __restrict__ ctx, const float* __restrict__ Whh,
            const float* __restrict__ Wih)
{
    extern __shared__ __align__(16) char dynsm[];
    float*  sgp    = (float*)(dynsm + SC_SG);
    float*  attq_s = (float*)(dynsm + SC_ATTQ);
    float*  sc_s   = (float*)(dynsm + SC_SC);
    float*  s_lse  = (float*)(dynsm + SC_LSE);
    const uint32_t smHb = smem_u32(dynsm);

    const int tid  = threadIdx.x;
    const int lane = tid & 31;
    const int w    = tid >> 5;
    const int blk  = blockIdx.x;
    const int j0   = blk * 4;
    const bool att_on = (blk & 1) == 0;
    const int cb   = blk >> 2;
    const int chalf = (blk >> 1) & 1;

    const int lr0 = 2*w, lr1 = 2*w + 1;
    const int n0 = (lr0 >> 2)*Hz + j0 + (lr0 & 3);
    const int n1 = (lr1 >> 2)*Hz + j0 + (lr1 & 3);

    ulonglong2 wA0[4], wA1[4], wB0[8], wB1[8];
    {
        const ulonglong2* W0 = (const ulonglong2*)(Whh + (size_t)n0*Hz);
        const ulonglong2* W1 = (const ulonglong2*)(Whh + (size_t)n1*Hz);
#pragma unroll
        for (int i = 0; i < 4; ++i) { wA0[i] = W0[lane + 32*i]; wA1[i] = W1[lane + 32*i]; }
        const ulonglong2* I0 = (const ulonglong2*)(Wih + (size_t)(Gz + n0)*Hz);
        const ulonglong2* I1 = (const ulonglong2*)(Wih + (size_t)(Gz + n1)*Hz);
        const ulonglong2* H0 = (const ulonglong2*)(Whh + (size_t)(Gz + n0)*Hz);
        const ulonglong2* H1 = (const ulonglong2*)(Whh + (size_t)(Gz + n1)*Hz);
#pragma unroll
        for (int i = 0; i < 4; ++i) {
            wB0[i]   = I0[lane + 32*i];  wB1[i]   = I1[lane + 32*i];
            wB0[4+i] = H0[lane + 32*i];  wB1[4+i] = H1[lane + 32*i];
        }
    }

    auto stageH = [&](const float4* src, int buf) {
        uint32_t db = smHb + buf*32768 + tid*16;
#pragma unroll
        for (int i = 0; i < 8; ++i)
            CP_ASYNC16_CG(db + i*NTHR*16, src + tid + i*NTHR);
        CP_COMMIT();
    };

    auto gates16 = [&](int buf, int boff, int slotbase,
                       const ulonglong2* wr0, const ulonglong2* wr1) {
        const ulonglong2* hb2 = (const ulonglong2*)(dynsm + buf*32768);
#pragma unroll 2
        for (int bl = 0; bl < 16; ++bl) {
            unsigned long long a0 = 0ull, a1 = 0ull;
            const ulonglong2* hr = hb2 + bl*128;
#pragma unroll
            for (int i = 0; i < 4; ++i) {
                ulonglong2 h2 = hr[lane + 32*i];
                ffma2(a0, h2.x, wr0[i].x); ffma2(a0, h2.y, wr0[i].y);
                ffma2(a1, h2.x, wr1[i].x); ffma2(a1, h2.y, wr1[i].y);
            }
            float2 f0 = unpack2(a0), f1 = unpack2(a1);
            float s0 = f0.x + f0.y, s1 = f1.x + f1.y;
            s0 += __shfl_xor_sync(0xffffffffu, s0, 16);
            s1 += __shfl_xor_sync(0xffffffffu, s1, 16);
            s0 += __shfl_xor_sync(0xffffffffu, s0, 8);
            s1 += __shfl_xor_sync(0xffffffffu, s1, 8);
            if (lane < 8) {
                int b = boff + bl;
                sgp[(lr0*32 + b)*16 + slotbase + lane] = s0;
                sgp[(lr1*32 + b)*16 + slotbase + lane] = s1;
            }
        }
    };

    unsigned nbar = 0;

    for (int t = 0; t < Tz; ++t) {
        const int p = t & 1;
        const float* h0p = d_h0buf + p*Bz*Hz;
        float*       h0n = d_h0buf + (p^1)*Bz*Hz;
        const float* h1p = d_h1buf + p*Bz*Hz;
        float*       h1n = d_h1buf + (p^1)*Bz*Hz;

        // ===== Phase A =====
        {
            const float4* Hp = (const float4*)h0p;
            stageH(Hp, 0);
            stageH(Hp + 2048, 1);
            CP_WAIT(1); __syncthreads();
            gates16(0, 0, 0, wA0, wA1);
            CP_WAIT(0); __syncthreads();
            gates16(1, 16, 0, wA0, wA1);
            __syncthreads();
            if (tid < 128) {
                int b = tid >> 2, jj = tid & 3;
                int j = j0 + jj;
                const float* seed = d_g0ih + ((size_t)t*Bz + b)*Gz;
                float g4[4];
#pragma unroll
                for (int g = 0; g < 4; ++g) {
                    const float4* q = (const float4*)&sgp[((g*4 + jj)*32 + b)*16];
                    float4 q0 = q[0], q1 = q[1];
                    g4[g] = (q0.x + q0.y) + (q0.z + q0.w) + (q1.x + q1.y) + (q1.z + q1.w);
                }
                float gi = g4[0] + seed[j];
                float gf = g4[1] + seed[Hz + j];
                float gg = g4[2] + seed[2*Hz + j];
                float go = g4[3] + seed[3*Hz + j];
                int ci = b*Hz + j;
                float c = sigf(gf)*d_cstate[ci] + sigf(gi)*tanhf(gg);
                float h = sigf(go)*tanhf(c);
                d_cstate[ci] = c;
                __stcg(&h0n[ci], h);
                __stcg(&d_cat1[ci], h + d_x[((size_t)t*Bz + b)*Hz + j]);
            }
        }
        gbar(nbar, blk);

        // ===== Phase B =====
        {
            const float4* srcs[4] = { (const float4*)d_cat1, (const float4*)d_cat1 + 2048,
                                      (const float4*)h1p,    (const float4*)h1p + 2048 };
            stageH(srcs[0], 0);
            stageH(srcs[1], 1);
#pragma unroll
            for (int r = 0; r < 4; ++r) {
                CP_WAIT(1); __syncthreads();
                const ulonglong2* wr0 = (r < 2) ? wB0 : (wB0 + 4);
                const ulonglong2* wr1 = (r < 2) ? wB1 : (wB1 + 4);
                gates16(r & 1, (r & 1)*16, (r < 2) ? 0 : 8, wr0, wr1);
                __syncthreads();
                if (r + 2 < 4) stageH(srcs[r + 2], r & 1);
                if (r == 2) { CP_WAIT(0); }
            }
            __syncthreads();
            if (tid < 128) {
                int b = tid >> 2, jj = tid & 3;
                int j = j0 + jj;
                float g4[4];
#pragma unroll
                for (int g = 0; g < 4; ++g) {
                    const float4* q = (const float4*)&sgp[((g*4 + jj)*32 + b)*16];
                    float4 q0 = q[0], q1 = q[1], q2 = q[2], q3 = q[3];
                    g4[g] = ((q0.x + q0.y) + (q0.z + q0.w)) + ((q1.x + q1.y) + (q1.z + q1.w))
                          + ((q2.x + q2.y) + (q2.z + q2.w)) + ((q3.x + q3.y) + (q3.z + q3.w));
                }
                float gi = g4[0] + d_bias1[j];
                float gf = g4[1] + d_bias1[Hz + j];
                float gg = g4[2] + d_bias1[2*Hz + j];
                float go = g4[3] + d_bias1[3*Hz + j];
                int ci = Bz*Hz + b*Hz + j;
                float c = sigf(gf)*d_cstate[ci] + sigf(gi)*tanhf(gg);
                float h = sigf(go)*tanhf(c);
                d_cstate[ci] = c;
                __stcg(&h1n[b*Hz + j], h);
                __stcg(&d_attq[b*Hz + j], h + __ldcg(&d_cat1[b*Hz + j]));
            }
        }
        gbar(nbar, blk);

        // ===== Phase C (even blocks; batch cb, H-half chalf) =====
        if (att_on) {
            for (int i = tid; i < Hz; i += NTHR) attq_s[i] = __ldcg(&d_attq[cb*Hz + i]);
            __syncthreads();

            const float4* A4 = (const float4*)attq_s;
            for (int s = w*16; s < w*16 + 16; ++s) {
                const float4* C4 = (const float4*)(ctx + ((size_t)cb*Sz + s)*Hz);
                float acc = 0.f;
#pragma unroll
                for (int i = 0; i < 4; ++i) {
                    float4 c4 = C4[lane + 32*i];
                    float4 a4 = A4[lane + 32*i];
                    acc += c4.x*a4.x + c4.y*a4.y + c4.z*a4.z + c4.w*a4.w;
                }
#pragma unroll
                for (int o = 16; o; o >>= 1) acc += __shfl_xor_sync(0xffffffffu, acc, o);
                if (lane == 0) sc_s[s] = acc;
            }
            __syncthreads();

            if (w == 0) {
                float m = -1e30f;
                for (int s = lane; s < Sz; s += 32) m = fmaxf(m, sc_s[s]);
#pragma unroll
                for (int o = 16; o; o >>= 1) m = fmaxf(m, __shfl_xor_sync(0xffffffffu, m, o));
                float sm = 0.f;
                for (int s = lane; s < Sz; s += 32) sm += expf(sc_s[s] - m);
#pragma unroll
                for (int o = 16; o; o >>= 1) sm += __shfl_xor_sync(0xffffffffu, sm, o);
                if (lane == 0) *s_lse = m + logf(sm);
            }
            __syncthreads();
            float lse = *s_lse;

            int h = chalf*256 + tid;
            const float* cp = ctx + (size_t)cb*Sz*Hz + h;
            float acc = 0.f;
#pragma unroll 8
            for (int s = 0; s < Sz; ++s)
                acc += cp[(size_t)s*Hz] * (sc_s[s] - lse);
            size_t oi = ((size_t)cb*Tz + t)*Hz + h;
            __nv_bfloat16 hv = __float2bfloat16(acc);
            d_out_hi[oi] = hv;
            d_out_lo[oi] = __float2bfloat16(acc - __bfloat162float(hv));
            __syncthreads();
        }
    }
}

// ---------------- tail: hT, cT ----------------
__global__ void tail_kernel(float* __restrict__ out)
{
    int i = blockIdx.x * blockDim.x + threadIdx.x;
    const size_t base = (size_t)Bz*Tz*Vz;
    if (i < Bz*Hz)                 out[base + i] = d_h0buf[i];
    else if (i < 2*Bz*Hz)          out[base + i] = d_h1buf[i - Bz*Hz];
    else if (i < 4*Bz*Hz)          out[base + i] = d_cstate[i - 2*Bz*Hz];
}

// ---------------- launch ----------------
extern "C" void kernel_launch(void* const* d_in, const int* in_sizes, int n_in,
                              void* d_out, int out_size)
{
    const float* context = (const float*)d_in[0];
    const int*   dec     = (const int*)d_in[1];
    const float* h0      = (const float*)d_in[2];
    const float* c0      = (const float*)d_in[3];
    const float* emb     = (const float*)d_in[4];
    const float* Wih     = (const float*)d_in[5];
    const float* Whh     = (const float*)d_in[6];
    const float* bih     = (const float*)d_in[7];
    const float* bhh     = (const float*)d_in[8];
    const float* Wc      = (const float*)d_in[9];
    const float* bc      = (const float*)d_in[10];
    float* out = (float*)d_out;

    float *p_g0ih, *p_b0;
    __nv_bfloat16 *p_wch, *p_wcl, *p_oh, *p_ol, *p_xh, *p_xl, *p_wih, *p_wil;
    cudaGetSymbolAddress((void**)&p_g0ih, d_g0ih);
    cudaGetSymbolAddress((void**)&p_b0,   d_bias0);
    cudaGetSymbolAddress((void**)&p_wch,  d_Wc_hi);
    cudaGetSymbolAddress((void**)&p_wcl,  d_Wc_lo);
    cudaGetSymbolAddress((void**)&p_oh,   d_out_hi);
    cudaGetSymbolAddress((void**)&p_ol,   d_out_lo);
    cudaGetSymbolAddress((void**)&p_xh,   d_x_hi);
    cudaGetSymbolAddress((void**)&p_xl,   d_x_lo);
    cudaGetSymbolAddress((void**)&p_wih,  d_Wih0_hi);
    cudaGetSymbolAddress((void**)&p_wil,  d_Wih0_lo);

    const int SMEM_MMA = 2 * BUFB;   // 81920 -> 2 CTAs/SM
    cudaFuncSetAttribute(mma_gemm_kernel,
                         cudaFuncAttributeMaxDynamicSharedMemorySize, SMEM_MMA);
    cudaFuncSetAttribute(scan_kernel,
                         cudaFuncAttributeMaxDynamicSharedMemorySize, SC_TOTAL);

    init_kernel<<<(Tz*Bz*Hz + 255)/256, 256>>>(dec, emb, bih, bhh, h0, c0);

    {
        size_t n4 = (size_t)Vz*Hz/4;
        split_kernel<<<(unsigned)((n4 + 255)/256), 256>>>((const float4*)Wc, (uint2*)p_wch, (uint2*)p_wcl, n4);
        size_t m4 = (size_t)Gz*Hz/4;
        split_kernel<<<(unsigned)((m4 + 255)/256), 256>>>((const float4*)Wih, (uint2*)p_wih, (uint2*)p_wil, m4);
    }

    // g0ih = x @ Wih0^T + bias0
    {
        dim3 grid(Gz/128, (Tz*Bz)/128);
        mma_gemm_kernel<<<grid, 256, SMEM_MMA>>>(p_xh, p_xl, p_wih, p_wil, p_b0, p_g0ih, Gz);
    }

    // persistent scan
    scan_kernel<<<NBLK, NTHR, SC_TOTAL>>>(context, Whh, Wih);

    // logits = outs @ Wc^T + bc
    {
        dim3 grid(Vz/128, (Bz*Tz)/128);
        mma_gemm_kernel<<<grid, 256, SMEM_MMA>>>(p_oh, p_ol, p_wch, p_wcl, bc, out, Vz);
    }

    if ((long long)out_size >= (long long)Bz*Tz*Vz + 4LL*Bz*Hz) {
        tail_kernel<<<(4*Bz*Hz + 255)/256, 256>>>(out);
    }
}

// round 14
// speedup vs baseline: 1.1165x; 1.0495x over previous
#include <cuda_runtime.h>
#include <cuda_bf16.h>
#include <math.h>
#include <stdint.h>

#define Bz 32
#define Tz 64
#define Sz 128
#define Hz 512
#define Vz 32000
#define Gz 2048   // 4*H
#define NBLK 128
#define NTHR 256

// ---------------- device scratch ----------------
__device__ __align__(16) float d_x[Tz*Bz*Hz];
__device__ __align__(16) float d_g0ih[Tz*Bz*Gz];
__device__ __align__(16) float d_h0buf[2*Bz*Hz];
__device__ __align__(16) float d_h1buf[2*Bz*Hz];
__device__ __align__(16) float d_cstate[2*Bz*Hz];
__device__ __align__(16) float d_cat1[Bz*Hz];
__device__ __align__(16) float d_attq[Bz*Hz];
__device__ float d_bias0[Gz];
__device__ float d_bias1[Gz];
__device__ __align__(128) unsigned d_bar_cnt8[8*32];   // 8 counters, 128B apart
// bf16 hi/lo splits
__device__ __align__(16) __nv_bfloat16 d_Wc_hi[(size_t)Vz*Hz];
__device__ __align__(16) __nv_bfloat16 d_Wc_lo[(size_t)Vz*Hz];
__device__ __align__(16) __nv_bfloat16 d_out_hi[Bz*Tz*Hz];
__device__ __align__(16) __nv_bfloat16 d_out_lo[Bz*Tz*Hz];
__device__ __align__(16) __nv_bfloat16 d_x_hi[Tz*Bz*Hz];
__device__ __align__(16) __nv_bfloat16 d_x_lo[Tz*Bz*Hz];
__device__ __align__(16) __nv_bfloat16 d_Wih0_hi[Gz*Hz];
__device__ __align__(16) __nv_bfloat16 d_Wih0_lo[Gz*Hz];

__device__ __forceinline__ float sigf(float x) { return 1.f / (1.f + expf(-x)); }

// ---------------- packed f32x2 helpers ----------------
__device__ __forceinline__ void ffma2(unsigned long long &d,
                                      unsigned long long a,
                                      unsigned long long b)
{
    asm("fma.rn.f32x2 %0, %1, %2, %0;" : "+l"(d) : "l"(a), "l"(b));
}
__device__ __forceinline__ float2 unpack2(unsigned long long v)
{
    unsigned lo, hi;
    asm("mov.b64 {%0, %1}, %2;" : "=r"(lo), "=r"(hi) : "l"(v));
    return make_float2(__uint_as_float(lo), __uint_as_float(hi));
}

// ---------------- mma.sync / ldmatrix / cp.async helpers ----------------
__device__ __forceinline__ uint32_t smem_u32(const void* p) {
    uint32_t a;
    asm("{ .reg .u64 t; cvta.to.shared.u64 t, %1; cvt.u32.u64 %0, t; }" : "=r"(a) : "l"(p));
    return a;
}
__device__ __forceinline__ void ldsm4(uint32_t (&r)[4], uint32_t addr)
{
    asm volatile("ldmatrix.sync.aligned.m8n8.x4.shared.b16 {%0,%1,%2,%3}, [%4];"
                 : "=r"(r[0]), "=r"(r[1]), "=r"(r[2]), "=r"(r[3]) : "r"(addr));
}
__device__ __forceinline__ void mma_bf16(float (&c)[4], const uint32_t (&a)[4],
                                         const uint32_t* b)
{
    asm volatile(
        "mma.sync.aligned.m16n8k16.row.col.f32.bf16.bf16.f32 "
        "{%0,%1,%2,%3}, {%4,%5,%6,%7}, {%8,%9}, {%0,%1,%2,%3};"
        : "+f"(c[0]), "+f"(c[1]), "+f"(c[2]), "+f"(c[3])
        : "r"(a[0]), "r"(a[1]), "r"(a[2]), "r"(a[3]), "r"(b[0]), "r"(b[1]));
}
#define CP_ASYNC16_CG(dst, src) \
    asm volatile("cp.async.cg.shared.global [%0], [%1], 16;" :: "r"(dst), "l"(src))
#define CP_COMMIT() asm volatile("cp.async.commit_group;" ::: "memory")
#define CP_WAIT(n)  asm volatile("cp.async.wait_group %0;" :: "n"(n) : "memory")

// ---------------- grid barrier: 8 distributed counters ----------------
__device__ __forceinline__ void gbar(unsigned &nbar, int blk)
{
    nbar++;
    __syncthreads();
    if (threadIdx.x == 0) {
        __threadfence();
        atomicAdd(&d_bar_cnt8[(blk & 7) * 32], 1u);
        const unsigned target = nbar * (NBLK / 8);
        for (;;) {
            bool done = true;
#pragma unroll
            for (int i = 0; i < 8; ++i)
                done &= (*(volatile unsigned*)&d_bar_cnt8[i * 32] >= target);
            if (done) break;
        }
    }
    __syncthreads();
}

// ---------------- fused init ----------------
__global__ void init_kernel(const int* __restrict__ ids32, const float* __restrict__ emb,
                            const float* __restrict__ bih, const float* __restrict__ bhh,
                            const float* __restrict__ h0, const float* __restrict__ c0)
{
    int i = blockIdx.x * blockDim.x + threadIdx.x;
    if (i < 8) d_bar_cnt8[i * 32] = 0u;
    if (i < Gz) {
        d_bias0[i] = bih[i] + bhh[i];
        d_bias1[i] = bih[Gz + i] + bhh[Gz + i];
    }
    if (i < Bz*Hz) {
        d_h0buf[i] = h0[i];
        d_h1buf[i] = h0[Bz*Hz + i];
    }
    if (i < 2*Bz*Hz) d_cstate[i] = c0[i];
    if (i < Tz*Bz*Hz) {
        bool is64 = (ids32[1] == 0) && (ids32[3] == 0) && (ids32[5] == 0);
        int h = i % Hz;
        int tb = i / Hz;
        int b = tb % Bz;
        int t = tb / Bz;
        int idx = b*Tz + t;
        int id = is64 ? ids32[2*idx] : ids32[idx];
        if (id < 0 || id >= Vz) id = 0;
        float v = (id == 0) ? 0.f : emb[(size_t)id*Hz + h];
        d_x[i] = v;
        __nv_bfloat16 hv = __float2bfloat16(v);
        d_x_hi[i] = hv;
        d_x_lo[i] = __float2bfloat16(v - __bfloat162float(hv));
    }
}

// ---------------- hi/lo bf16 split (vectorized) ----------------
__global__ void split_kernel(const float4* __restrict__ src,
                             uint2* __restrict__ hi,
                             uint2* __restrict__ lo, size_t n4)
{
    size_t i = (size_t)blockIdx.x * blockDim.x + threadIdx.x;
    if (i >= n4) return;
    float4 v = src[i];
    __nv_bfloat16 hx = __float2bfloat16(v.x);
    __nv_bfloat16 hy = __float2bfloat16(v.y);
    __nv_bfloat16 hz = __float2bfloat16(v.z);
    __nv_bfloat16 hw = __float2bfloat16(v.w);
    __nv_bfloat16 lx = __float2bfloat16(v.x - __bfloat162float(hx));
    __nv_bfloat16 ly = __float2bfloat16(v.y - __bfloat162float(hy));
    __nv_bfloat16 lz = __float2bfloat16(v.z - __bfloat162float(hz));
    __nv_bfloat16 lw = __float2bfloat16(v.w - __bfloat162float(hw));
    uint2 ho, lu;
    ho.x = (uint32_t)__bfloat16_as_ushort(hx) | ((uint32_t)__bfloat16_as_ushort(hy) << 16);
    ho.y = (uint32_t)__bfloat16_as_ushort(hz) | ((uint32_t)__bfloat16_as_ushort(hw) << 16);
    lu.x = (uint32_t)__bfloat16_as_ushort(lx) | ((uint32_t)__bfloat16_as_ushort(ly) << 16);
    lu.y = (uint32_t)__bfloat16_as_ushort(lz) | ((uint32_t)__bfloat16_as_ushort(lw) << 16);
    hi[i] = ho;
    lo[i] = lu;
}

// ---------------- bf16-split mma GEMM (8 warps, 64x32 warp tile) --------------
#define KC    32
#define KCP   40
#define ARRB  (128*KCP*2)                // 10240
#define BUFB  (4*ARRB)                   // 40960

__global__ void __launch_bounds__(256, 2)
mma_gemm_kernel(const __nv_bfloat16* __restrict__ Ahi, const __nv_bfloat16* __restrict__ Alo,
                const __nv_bfloat16* __restrict__ Bhi, const __nv_bfloat16* __restrict__ Blo,
                const float* __restrict__ bias, float* __restrict__ C, int ldc)
{
    extern __shared__ __align__(16) char sm_raw[];

    const int tid  = threadIdx.x;
    const int lane = tid & 31;
    const int wid  = tid >> 5;
    const int wm   = wid >> 2;
    const int wn   = wid & 3;
    const int n0   = blockIdx.x * 128;
    const int m0   = blockIdx.y * 128;

    float acc[4][4][4];
#pragma unroll
    for (int i = 0; i < 4; ++i)
#pragma unroll
        for (int j = 0; j < 4; ++j)
#pragma unroll
            for (int v = 0; v < 4; ++v) acc[i][j][v] = 0.f;

    const int gr = tid >> 1;
    const int gs = (tid & 1) * 2;

    const uint32_t smBase = smem_u32(sm_raw);

    auto stage = [&](int c, int buf) {
        const int k0 = c * KC;
        uint32_t db = smBase + buf*BUFB + gr*(KCP*2) + gs*16;
        const __nv_bfloat16* pAh = Ahi + (size_t)(m0 + gr)*Hz + k0 + gs*8;
        const __nv_bfloat16* pAl = Alo + (size_t)(m0 + gr)*Hz + k0 + gs*8;
        const __nv_bfloat16* pBh = Bhi + (size_t)(n0 + gr)*Hz + k0 + gs*8;
        const __nv_bfloat16* pBl = Blo + (size_t)(n0 + gr)*Hz + k0 + gs*8;
#pragma unroll
        for (int i = 0; i < 2; ++i) {
            CP_ASYNC16_CG(db + i*16 + 0*ARRB, pAh + i*8);
            CP_ASYNC16_CG(db + i*16 + 1*ARRB, pAl + i*8);
            CP_ASYNC16_CG(db + i*16 + 2*ARRB, pBh + i*8);
            CP_ASYNC16_CG(db + i*16 + 3*ARRB, pBl + i*8);
        }
        CP_COMMIT();
    };

    const int NCHUNK = Hz / KC;   // 16
    stage(0, 0);

    for (int c = 0; c < NCHUNK; ++c) {
        if (c + 1 < NCHUNK) { stage(c + 1, (c + 1) & 1); CP_WAIT(1); }
        else                { CP_WAIT(0); }
        __syncthreads();

        const uint32_t bb  = smBase + (c & 1)*BUFB;
        const uint32_t uAh = bb;
        const uint32_t uAl = bb + 1*ARRB;
        const uint32_t uBh = bb + 2*ARRB;
        const uint32_t uBl = bb + 3*ARRB;

#pragma unroll
        for (int ks = 0; ks < KC/16; ++ks) {
            uint32_t fAh[4][4], fAl[4][4], fBh[4][2], fBl[4][2];
            const int arow = wm*64 + (lane & 15);
            const int acol = ks*16 + ((lane >> 4) << 3);
#pragma unroll
            for (int mt = 0; mt < 4; ++mt) {
                uint32_t off = ((arow + mt*16)*KCP + acol) * 2;
                ldsm4(fAh[mt], uAh + off);
                ldsm4(fAl[mt], uAl + off);
            }
            const int brow = wn*32 + (lane & 7) + ((lane >> 4) << 3);
            const int bcol = ks*16 + (lane & 8);
#pragma unroll
            for (int p = 0; p < 2; ++p) {
                uint32_t off = ((brow + p*16)*KCP + bcol) * 2;
                uint32_t t4[4];
                ldsm4(t4, uBh + off);
                fBh[2*p][0] = t4[0]; fBh[2*p][1] = t4[1];
                fBh[2*p+1][0] = t4[2]; fBh[2*p+1][1] = t4[3];
                ldsm4(t4, uBl + off);
                fBl[2*p][0] = t4[0]; fBl[2*p][1] = t4[1];
                fBl[2*p+1][0] = t4[2]; fBl[2*p+1][1] = t4[3];
            }
#pragma unroll
            for (int mt = 0; mt < 4; ++mt)
#pragma unroll
                for (int nt = 0; nt < 4; ++nt) mma_bf16(acc[mt][nt], fAh[mt], fBh[nt]);
#pragma unroll
            for (int mt = 0; mt < 4; ++mt)
#pragma unroll
                for (int nt = 0; nt < 4; ++nt) mma_bf16(acc[mt][nt], fAh[mt], fBl[nt]);
#pragma unroll
            for (int mt = 0; mt < 4; ++mt)
#pragma unroll
                for (int nt = 0; nt < 4; ++nt) mma_bf16(acc[mt][nt], fAl[mt], fBh[nt]);
        }
        __syncthreads();
    }

    const int gid = lane >> 2;
    const int tig = lane & 3;
#pragma unroll
    for (int mt = 0; mt < 4; ++mt) {
        int mA = m0 + wm*64 + mt*16 + gid;
#pragma unroll
        for (int nt = 0; nt < 4; ++nt) {
            int n = n0 + wn*32 + nt*8 + tig*2;
            float2 bv = *(const float2*)&bias[n];
            float2 v0 = make_float2(acc[mt][nt][0] + bv.x, acc[mt][nt][1] + bv.y);
            float2 v1 = make_float2(acc[mt][nt][2] + bv.x, acc[mt][nt][3] + bv.y);
            *(float2*)&C[(size_t)mA*ldc + n]     = v0;
            *(float2*)&C[(size_t)(mA+8)*ldc + n] = v1;
        }
    }
}

// ---------------- persistent scan: 4 rows/warp, batch-split halves -----------
// dynamic smem: 4 x 32KB staging + 32KB partials + attention scratch
#define SC_HB     0                          // 4 x 32768
#define SC_SG     131072                     // 16*32*16*4 = 32768
#define SC_ATTQ   (SC_SG + 32768)            // 2048
#define SC_SC     (SC_ATTQ + 2048)           // 512
#define SC_LSE    (SC_SC + 512)              // 16
#define SC_TOTAL  (SC_LSE + 16)

__global__ void __launch_bounds__(NTHR, 1)
scan_kernel(const float* __restrict__ ctx, const float* __restrict__ Whh,
            const float* __restrict__ Wih)
{
    extern __shared__ __align__(16) char dynsm[];
    float*  sgp    = (float*)(dynsm + SC_SG);
    float*  attq_s = (float*)(dynsm + SC_ATTQ);
    float*  sc_s   = (float*)(dynsm + SC_SC);
    float*  s_lse  = (float*)(dynsm + SC_LSE);
    const uint32_t smHb = smem_u32(dynsm);

    const int tid  = threadIdx.x;
    const int lane = tid & 31;
    const int w    = tid >> 5;
    const int wg   = w & 3;      // gate index (4 rows)
    const int bh   = w >> 2;     // batch half (0: b 0-15, 1: b 16-31)
    const int blk  = blockIdx.x;
    const int j0   = blk * 4;
    const bool att_on = (blk & 1) == 0;
    const int cb   = blk >> 2;
    const int chalf = (blk >> 1) & 1;

    // persistent layer0 Whh weights: rows n = wg*Hz + j0 + jj
    ulonglong2 wA[4][4];
#pragma unroll
    for (int jj = 0; jj < 4; ++jj) {
        const ulonglong2* W = (const ulonglong2*)(Whh + (size_t)(wg*Hz + j0 + jj)*Hz);
#pragma unroll
        for (int i = 0; i < 4; ++i) wA[jj][i] = W[lane + 32*i];
    }
    // active layer1 B-half weights (reloaded per step)
    ulonglong2 wB[4][4];
    auto loadB = [&](const float* Wsrc) {
#pragma unroll
        for (int jj = 0; jj < 4; ++jj) {
            const ulonglong2* W = (const ulonglong2*)(Wsrc + (size_t)(Gz + wg*Hz + j0 + jj)*Hz);
#pragma unroll
            for (int i = 0; i < 4; ++i) wB[jj][i] = W[lane + 32*i];
        }
    };
    loadB(Wih);

    auto stageH = [&](const float4* src, int buf) {
        uint32_t db = smHb + buf*32768 + tid*16;
#pragma unroll
        for (int i = 0; i < 8; ++i)
            CP_ASYNC16_CG(db + i*NTHR*16, src + tid + i*NTHR);
        CP_COMMIT();
    };

    // gate GEMV: 4 rows x 16 batches from one staged buffer
    auto gates4 = [&](int buf, int boff, int slotbase, ulonglong2 (&wt)[4][4]) {
        const ulonglong2* hb2 = (const ulonglong2*)(dynsm + buf*32768);
#pragma unroll 2
        for (int bl = 0; bl < 16; ++bl) {
            ulonglong2 h2[4];
#pragma unroll
            for (int i = 0; i < 4; ++i) h2[i] = hb2[bl*128 + lane + 32*i];
            unsigned long long a0 = 0ull, a1 = 0ull, a2 = 0ull, a3 = 0ull;
#pragma unroll
            for (int i = 0; i < 4; ++i) {
                ffma2(a0, h2[i].x, wt[0][i].x); ffma2(a0, h2[i].y, wt[0][i].y);
                ffma2(a1, h2[i].x, wt[1][i].x); ffma2(a1, h2[i].y, wt[1][i].y);
                ffma2(a2, h2[i].x, wt[2][i].x); ffma2(a2, h2[i].y, wt[2][i].y);
                ffma2(a3, h2[i].x, wt[3][i].x); ffma2(a3, h2[i].y, wt[3][i].y);
            }
            float s[4];
            float2 f0 = unpack2(a0); s[0] = f0.x + f0.y;
            float2 f1 = unpack2(a1); s[1] = f1.x + f1.y;
            float2 f2 = unpack2(a2); s[2] = f2.x + f2.y;
            float2 f3 = unpack2(a3); s[3] = f3.x + f3.y;
#pragma unroll
            for (int jj = 0; jj < 4; ++jj) {
                s[jj] += __shfl_xor_sync(0xffffffffu, s[jj], 16);
                s[jj] += __shfl_xor_sync(0xffffffffu, s[jj], 8);
            }
            if (lane < 8) {
                int b = boff + bl;
#pragma unroll
                for (int jj = 0; jj < 4; ++jj)
                    sgp[((wg*4 + jj)*32 + b)*16 + slotbase + lane] = s[jj];
            }
        }
    };

    unsigned nbar = 0;

    for (int t = 0; t < Tz; ++t) {
        const int p = t & 1;
        const float* h0p = d_h0buf + p*Bz*Hz;
        float*       h0n = d_h0buf + (p^1)*Bz*Hz;
        const float* h1p = d_h1buf + p*Bz*Hz;
        float*       h1n = d_h1buf + (p^1)*Bz*Hz;

        // ===== Phase A: layer0 gates =====
        {
            const float4* Hp = (const float4*)h0p;
            stageH(Hp, 0);          // batches 0-15
            stageH(Hp + 2048, 1);   // batches 16-31
            if (bh == 0) { CP_WAIT(1); gates4(0, 0,  0, wA); }
            else         { CP_WAIT(0); gates4(1, 16, 0, wA); }
            __syncthreads();
            if (tid < 128) {
                int b = tid >> 2, jj = tid & 3;
                int j = j0 + jj;
                const float* seed = d_g0ih + ((size_t)t*Bz + b)*Gz;
                float g4[4];
#pragma unroll
                for (int g = 0; g < 4; ++g) {
                    const float4* q = (const float4*)&sgp[((g*4 + jj)*32 + b)*16];
                    float4 q0 = q[0], q1 = q[1];
                    g4[g] = (q0.x + q0.y) + (q0.z + q0.w) + (q1.x + q1.y) + (q1.z + q1.w);
                }
                float gi = g4[0] + seed[j];
                float gf = g4[1] + seed[Hz + j];
                float gg = g4[2] + seed[2*Hz + j];
                float go = g4[3] + seed[3*Hz + j];
                int ci = b*Hz + j;
                float c = sigf(gf)*d_cstate[ci] + sigf(gi)*tanhf(gg);
                float h = sigf(go)*tanhf(c);
                d_cstate[ci] = c;
                __stcg(&h0n[ci], h);
                __stcg(&d_cat1[ci], h + d_x[((size_t)t*Bz + b)*Hz + j]);
            }
        }
        gbar(nbar, blk);

        // ===== Phase B: layer1 gates (cat1 -> slots 0-7, h1 -> slots 8-15) =====
        {
            stageH((const float4*)d_cat1, 0);
            stageH((const float4*)d_cat1 + 2048, 1);
            stageH((const float4*)h1p, 2);
            stageH((const float4*)h1p + 2048, 3);
            if (bh == 0) {
                CP_WAIT(3); gates4(0, 0, 0, wB);        // cat1 x Wih1
                loadB(Whh);                              // switch to Whh1
                CP_WAIT(1); gates4(2, 0, 8, wB);        // h1 x Whh1
            } else {
                CP_WAIT(2); gates4(1, 16, 0, wB);
                loadB(Whh);
                CP_WAIT(0); gates4(3, 16, 8, wB);
            }
            loadB(Wih);   // restore Wih1 for next step (latency hidden by C/barrier)
            __syncthreads();
            if (tid < 128) {
                int b = tid >> 2, jj = tid & 3;
                int j = j0 + jj;
                float g4[4];
#pragma unroll
                for (int g = 0; g < 4; ++g) {
                    const float4* q = (const float4*)&sgp[((g*4 + jj)*32 + b)*16];
                    float4 q0 = q[0], q1 = q[1], q2 = q[2], q3 = q[3];
                    g4[g] = ((q0.x + q0.y) + (q0.z + q0.w)) + ((q1.x + q1.y) + (q1.z + q1.w))
                          + ((q2.x + q2.y) + (q2.z + q2.w)) + ((q3.x + q3.y) + (q3.z + q3.w));
                }
                float gi = g4[0] + d_bias1[j];
                float gf = g4[1] + d_bias1[Hz + j];
                float gg = g4[2] + d_bias1[2*Hz + j];
                float go = g4[3] + d_bias1[3*Hz + j];
                int ci = Bz*Hz + b*Hz + j;
                float c = sigf(gf)*d_cstate[ci] + sigf(gi)*tanhf(gg);
                float h = sigf(go)*tanhf(c);
                d_cstate[ci] = c;
                __stcg(&h1n[b*Hz + j], h);
                __stcg(&d_attq[b*Hz + j], h + __ldcg(&d_cat1[b*Hz + j]));
            }
        }
        gbar(nbar, blk);

        // ===== Phase C: attention (even blocks; batch cb, H-half chalf) =====
        if (att_on) {
            for (int i = tid; i < Hz; i += NTHR) attq_s[i] = __ldcg(&d_attq[cb*Hz + i]);
            __syncthreads();

            const float4* A4 = (const float4*)attq_s;
            for (int s = w*16; s < w*16 + 16; ++s) {
                const float4* C4 = (const float4*)(ctx + ((size_t)cb*Sz + s)*Hz);
                float acc = 0.f;
#pragma unroll
                for (int i = 0; i < 4; ++i) {
                    float4 c4 = C4[lane + 32*i];
                    float4 a4 = A4[lane + 32*i];
                    acc += c4.x*a4.x + c4.y*a4.y + c4.z*a4.z + c4.w*a4.w;
                }
#pragma unroll
                for (int o = 16; o; o >>= 1) acc += __shfl_xor_sync(0xffffffffu, acc, o);
                if (lane == 0) sc_s[s] = acc;
            }
            __syncthreads();

            if (w == 0) {
                float m = -1e30f;
                for (int s = lane; s < Sz; s += 32) m = fmaxf(m, sc_s[s]);
#pragma unroll
                for (int o = 16; o; o >>= 1) m = fmaxf(m, __shfl_xor_sync(0xffffffffu, m, o));
                float sm = 0.f;
                for (int s = lane; s < Sz; s += 32) sm += expf(sc_s[s] - m);
#pragma unroll
                for (int o = 16; o; o >>= 1) sm += __shfl_xor_sync(0xffffffffu, sm, o);
                if (lane == 0) *s_lse = m + logf(sm);
            }
            __syncthreads();
            float lse = *s_lse;

            int h = chalf*256 + tid;
            const float* cp = ctx + (size_t)cb*Sz*Hz + h;
            float acc = 0.f;
#pragma unroll 8
            for (int s = 0; s < Sz; ++s)
                acc += cp[(size_t)s*Hz] * (sc_s[s] - lse);
            size_t oi = ((size_t)cb*Tz + t)*Hz + h;
            __nv_bfloat16 hv = __float2bfloat16(acc);
            d_out_hi[oi] = hv;
            d_out_lo[oi] = __float2bfloat16(acc - __bfloat162float(hv));
            __syncthreads();
        }
    }
}

// ---------------- tail: hT, cT ----------------
__global__ void tail_kernel(float* __restrict__ out)
{
    int i = blockIdx.x * blockDim.x + threadIdx.x;
    const size_t base = (size_t)Bz*Tz*Vz;
    if (i < Bz*Hz)                 out[base + i] = d_h0buf[i];
    else if (i < 2*Bz*Hz)          out[base + i] = d_h1buf[i - Bz*Hz];
    else if (i < 4*Bz*Hz)          out[base + i] = d_cstate[i - 2*Bz*Hz];
}

// ---------------- launch ----------------
extern "C" void kernel_launch(void* const* d_in, const int* in_sizes, int n_in,
                              void* d_out, int out_size)
{
    const float* context = (const float*)d_in[0];
    const int*   dec     = (const int*)d_in[1];
    const float* h0      = (const float*)d_in[2];
    const float* c0      = (const float*)d_in[3];
    const float* emb     = (const float*)d_in[4];
    const float* Wih     = (const float*)d_in[5];
    const float* Whh     = (const float*)d_in[6];
    const float* bih     = (const float*)d_in[7];
    const float* bhh     = (const float*)d_in[8];
    const float* Wc      = (const float*)d_in[9];
    const float* bc      = (const float*)d_in[10];
    float* out = (float*)d_out;

    float *p_g0ih, *p_b0;
    __nv_bfloat16 *p_wch, *p_wcl, *p_oh, *p_ol, *p_xh, *p_xl, *p_wih, *p_wil;
    cudaGetSymbolAddress((void**)&p_g0ih, d_g0ih);
    cudaGetSymbolAddress((void**)&p_b0,   d_bias0);
    cudaGetSymbolAddress((void**)&p_wch,  d_Wc_hi);
    cudaGetSymbolAddress((void**)&p_wcl,  d_Wc_lo);
    cudaGetSymbolAddress((void**)&p_oh,   d_out_hi);
    cudaGetSymbolAddress((void**)&p_ol,   d_out_lo);
    cudaGetSymbolAddress((void**)&p_xh,   d_x_hi);
    cudaGetSymbolAddress((void**)&p_xl,   d_x_lo);
    cudaGetSymbolAddress((void**)&p_wih,  d_Wih0_hi);
    cudaGetSymbolAddress((void**)&p_wil,  d_Wih0_lo);

    const int SMEM_MMA = 2 * BUFB;   // 81920 -> 2 CTAs/SM
    cudaFuncSetAttribute(mma_gemm_kernel,
                         cudaFuncAttributeMaxDynamicSharedMemorySize, SMEM_MMA);
    cudaFuncSetAttribute(scan_kernel,
                         cudaFuncAttributeMaxDynamicSharedMemorySize, SC_TOTAL);

    init_kernel<<<(Tz*Bz*Hz + 255)/256, 256>>>(dec, emb, bih, bhh, h0, c0);

    {
        size_t n4 = (size_t)Vz*Hz/4;
        split_kernel<<<(unsigned)((n4 + 255)/256), 256>>>((const float4*)Wc, (uint2*)p_wch, (uint2*)p_wcl, n4);
        size_t m4 = (size_t)Gz*Hz/4;
        split_kernel<<<(unsigned)((m4 + 255)/256), 256>>>((const float4*)Wih, (uint2*)p_wih, (uint2*)p_wil, m4);
    }

    // g0ih = x @ Wih0^T + bias0
    {
        dim3 grid(Gz/128, (Tz*Bz)/128);
        mma_gemm_kernel<<<grid, 256, SMEM_MMA>>>(p_xh, p_xl, p_wih, p_wil, p_b0, p_g0ih, Gz);
    }

    // persistent scan
    scan_kernel<<<NBLK, NTHR, SC_TOTAL>>>(context, Whh, Wih);

    // logits = outs @ Wc^T + bc
    {
        dim3 grid(Vz/128, (Bz*Tz)/128);
        mma_gemm_kernel<<<grid, 256, SMEM_MMA>>>(p_oh, p_ol, p_wch, p_wcl, bc, out, Vz);
    }

    if ((long long)out_size >= (long long)Bz*Tz*Vz + 4LL*Bz*Hz) {
        tail_kernel<<<(4*Bz*Hz + 255)/256, 256>>>(out);
    }
}

// round 15
// speedup vs baseline: 1.1207x; 1.0037x over previous
#include <cuda_runtime.h>
#include <cuda_bf16.h>
#include <math.h>
#include <stdint.h>

#define Bz 32
#define Tz 64
#define Sz 128
#define Hz 512
#define Vz 32000
#define Gz 2048   // 4*H
#define NBLK 128
#define NTHR 256

// ---------------- device scratch ----------------
__device__ __align__(16) float d_x[Tz*Bz*Hz];
__device__ __align__(16) float d_g0ih[Tz*Bz*Gz];
__device__ __align__(16) float d_h0buf[2*Bz*Hz];
__device__ __align__(16) float d_h1buf[2*Bz*Hz];
__device__ __align__(16) float d_cstate[2*Bz*Hz];
__device__ __align__(16) float d_cat1[Bz*Hz];
__device__ __align__(16) float d_attq[Bz*Hz];
__device__ float d_bias0[Gz];
__device__ float d_bias1[Gz];
__device__ __align__(128) unsigned d_bar_cnt8[8*32];
// bf16 hi/lo splits
__device__ __align__(16) __nv_bfloat16 d_Wc_hi[(size_t)Vz*Hz];
__device__ __align__(16) __nv_bfloat16 d_Wc_lo[(size_t)Vz*Hz];
__device__ __align__(16) __nv_bfloat16 d_out_hi[Bz*Tz*Hz];
__device__ __align__(16) __nv_bfloat16 d_out_lo[Bz*Tz*Hz];
__device__ __align__(16) __nv_bfloat16 d_x_hi[Tz*Bz*Hz];
__device__ __align__(16) __nv_bfloat16 d_x_lo[Tz*Bz*Hz];
__device__ __align__(16) __nv_bfloat16 d_Wih0_hi[Gz*Hz];
__device__ __align__(16) __nv_bfloat16 d_Wih0_lo[Gz*Hz];

__device__ __forceinline__ float sigf(float x) { return 1.f / (1.f + expf(-x)); }

// ---------------- packed f32x2 helpers ----------------
__device__ __forceinline__ void ffma2(unsigned long long &d,
                                      unsigned long long a,
                                      unsigned long long b)
{
    asm("fma.rn.f32x2 %0, %1, %2, %0;" : "+l"(d) : "l"(a), "l"(b));
}
__device__ __forceinline__ float2 unpack2(unsigned long long v)
{
    unsigned lo, hi;
    asm("mov.b64 {%0, %1}, %2;" : "=r"(lo), "=r"(hi) : "l"(v));
    return make_float2(__uint_as_float(lo), __uint_as_float(hi));
}

// ---------------- mma.sync / ldmatrix / cp.async helpers ----------------
__device__ __forceinline__ uint32_t smem_u32(const void* p) {
    uint32_t a;
    asm("{ .reg .u64 t; cvta.to.shared.u64 t, %1; cvt.u32.u64 %0, t; }" : "=r"(a) : "l"(p));
    return a;
}
__device__ __forceinline__ void ldsm4(uint32_t (&r)[4], uint32_t addr)
{
    asm volatile("ldmatrix.sync.aligned.m8n8.x4.shared.b16 {%0,%1,%2,%3}, [%4];"
                 : "=r"(r[0]), "=r"(r[1]), "=r"(r[2]), "=r"(r[3]) : "r"(addr));
}
__device__ __forceinline__ void mma_bf16(float (&c)[4], const uint32_t (&a)[4],
                                         const uint32_t* b)
{
    asm volatile(
        "mma.sync.aligned.m16n8k16.row.col.f32.bf16.bf16.f32 "
        "{%0,%1,%2,%3}, {%4,%5,%6,%7}, {%8,%9}, {%0,%1,%2,%3};"
        : "+f"(c[0]), "+f"(c[1]), "+f"(c[2]), "+f"(c[3])
        : "r"(a[0]), "r"(a[1]), "r"(a[2]), "r"(a[3]), "r"(b[0]), "r"(b[1]));
}
#define CP_ASYNC16_CG(dst, src) \
    asm volatile("cp.async.cg.shared.global [%0], [%1], 16;" :: "r"(dst), "l"(src))
#define CP_COMMIT() asm volatile("cp.async.commit_group;" ::: "memory")
#define CP_WAIT(n)  asm volatile("cp.async.wait_group %0;" :: "n"(n) : "memory")

// ---------------- grid barrier: 8 distributed counters ----------------
__device__ __forceinline__ void gbar(unsigned &nbar, int blk)
{
    nbar++;
    __syncthreads();
    if (threadIdx.x == 0) {
        __threadfence();
        atomicAdd(&d_bar_cnt8[(blk & 7) * 32], 1u);
        const unsigned target = nbar * (NBLK / 8);
        for (;;) {
            bool done = true;
#pragma unroll
            for (int i = 0; i < 8; ++i)
                done &= (*(volatile unsigned*)&d_bar_cnt8[i * 32] >= target);
            if (done) break;
        }
    }
    __syncthreads();
}

// ---------------- fused init ----------------
__global__ void init_kernel(const int* __restrict__ ids32, const float* __restrict__ emb,
                            const float* __restrict__ bih, const float* __restrict__ bhh,
                            const float* __restrict__ h0, const float* __restrict__ c0)
{
    int i = blockIdx.x * blockDim.x + threadIdx.x;
    if (i < 8) d_bar_cnt8[i * 32] = 0u;
    if (i < Gz) {
        d_bias0[i] = bih[i] + bhh[i];
        d_bias1[i] = bih[Gz + i] + bhh[Gz + i];
    }
    if (i < Bz*Hz) {
        d_h0buf[i] = h0[i];
        d_h1buf[i] = h0[Bz*Hz + i];
    }
    if (i < 2*Bz*Hz) d_cstate[i] = c0[i];
    if (i < Tz*Bz*Hz) {
        bool is64 = (ids32[1] == 0) && (ids32[3] == 0) && (ids32[5] == 0);
        int h = i % Hz;
        int tb = i / Hz;
        int b = tb % Bz;
        int t = tb / Bz;
        int idx = b*Tz + t;
        int id = is64 ? ids32[2*idx] : ids32[idx];
        if (id < 0 || id >= Vz) id = 0;
        float v = (id == 0) ? 0.f : emb[(size_t)id*Hz + h];
        d_x[i] = v;
        __nv_bfloat16 hv = __float2bfloat16(v);
        d_x_hi[i] = hv;
        d_x_lo[i] = __float2bfloat16(v - __bfloat162float(hv));
    }
}

// ---------------- hi/lo bf16 split (vectorized) ----------------
__global__ void split_kernel(const float4* __restrict__ src,
                             uint2* __restrict__ hi,
                             uint2* __restrict__ lo, size_t n4)
{
    size_t i = (size_t)blockIdx.x * blockDim.x + threadIdx.x;
    if (i >= n4) return;
    float4 v = src[i];
    __nv_bfloat16 hx = __float2bfloat16(v.x);
    __nv_bfloat16 hy = __float2bfloat16(v.y);
    __nv_bfloat16 hz = __float2bfloat16(v.z);
    __nv_bfloat16 hw = __float2bfloat16(v.w);
    __nv_bfloat16 lx = __float2bfloat16(v.x - __bfloat162float(hx));
    __nv_bfloat16 ly = __float2bfloat16(v.y - __bfloat162float(hy));
    __nv_bfloat16 lz = __float2bfloat16(v.z - __bfloat162float(hz));
    __nv_bfloat16 lw = __float2bfloat16(v.w - __bfloat162float(hw));
    uint2 ho, lu;
    ho.x = (uint32_t)__bfloat16_as_ushort(hx) | ((uint32_t)__bfloat16_as_ushort(hy) << 16);
    ho.y = (uint32_t)__bfloat16_as_ushort(hz) | ((uint32_t)__bfloat16_as_ushort(hw) << 16);
    lu.x = (uint32_t)__bfloat16_as_ushort(lx) | ((uint32_t)__bfloat16_as_ushort(ly) << 16);
    lu.y = (uint32_t)__bfloat16_as_ushort(lz) | ((uint32_t)__bfloat16_as_ushort(lw) << 16);
    hi[i] = ho;
    lo[i] = lu;
}

// ---------------- bf16-split mma GEMM (8 warps, 64x32 warp tile) --------------
#define KC    32
#define KCP   40
#define ARRB  (128*KCP*2)                // 10240
#define BUFB  (4*ARRB)                   // 40960

__global__ void __launch_bounds__(256, 2)
mma_gemm_kernel(const __nv_bfloat16* __restrict__ Ahi, const __nv_bfloat16* __restrict__ Alo,
                const __nv_bfloat16* __restrict__ Bhi, const __nv_bfloat16* __restrict__ Blo,
                const float* __restrict__ bias, float* __restrict__ C, int ldc)
{
    extern __shared__ __align__(16) char sm_raw[];

    const int tid  = threadIdx.x;
    const int lane = tid & 31;
    const int wid  = tid >> 5;
    const int wm   = wid >> 2;
    const int wn   = wid & 3;
    const int n0   = blockIdx.x * 128;
    const int m0   = blockIdx.y * 128;

    float acc[4][4][4];
#pragma unroll
    for (int i = 0; i < 4; ++i)
#pragma unroll
        for (int j = 0; j < 4; ++j)
#pragma unroll
            for (int v = 0; v < 4; ++v) acc[i][j][v] = 0.f;

    const int gr = tid >> 1;
    const int gs = (tid & 1) * 2;

    const uint32_t smBase = smem_u32(sm_raw);

    auto stage = [&](int c, int buf) {
        const int k0 = c * KC;
        uint32_t db = smBase + buf*BUFB + gr*(KCP*2) + gs*16;
        const __nv_bfloat16* pAh = Ahi + (size_t)(m0 + gr)*Hz + k0 + gs*8;
        const __nv_bfloat16* pAl = Alo + (size_t)(m0 + gr)*Hz + k0 + gs*8;
        const __nv_bfloat16* pBh = Bhi + (size_t)(n0 + gr)*Hz + k0 + gs*8;
        const __nv_bfloat16* pBl = Blo + (size_t)(n0 + gr)*Hz + k0 + gs*8;
#pragma unroll
        for (int i = 0; i < 2; ++i) {
            CP_ASYNC16_CG(db + i*16 + 0*ARRB, pAh + i*8);
            CP_ASYNC16_CG(db + i*16 + 1*ARRB, pAl + i*8);
            CP_ASYNC16_CG(db + i*16 + 2*ARRB, pBh + i*8);
            CP_ASYNC16_CG(db + i*16 + 3*ARRB, pBl + i*8);
        }
        CP_COMMIT();
    };

    const int NCHUNK = Hz / KC;   // 16
    stage(0, 0);

    for (int c = 0; c < NCHUNK; ++c) {
        if (c + 1 < NCHUNK) { stage(c + 1, (c + 1) & 1); CP_WAIT(1); }
        else                { CP_WAIT(0); }
        __syncthreads();

        const uint32_t bb  = smBase + (c & 1)*BUFB;
        const uint32_t uAh = bb;
        const uint32_t uAl = bb + 1*ARRB;
        const uint32_t uBh = bb + 2*ARRB;
        const uint32_t uBl = bb + 3*ARRB;

#pragma unroll
        for (int ks = 0; ks < KC/16; ++ks) {
            uint32_t fAh[4][4], fAl[4][4], fBh[4][2], fBl[4][2];
            const int arow = wm*64 + (lane & 15);
            const int acol = ks*16 + ((lane >> 4) << 3);
#pragma unroll
            for (int mt = 0; mt < 4; ++mt) {
                uint32_t off = ((arow + mt*16)*KCP + acol) * 2;
                ldsm4(fAh[mt], uAh + off);
                ldsm4(fAl[mt], uAl + off);
            }
            const int brow = wn*32 + (lane & 7) + ((lane >> 4) << 3);
            const int bcol = ks*16 + (lane & 8);
#pragma unroll
            for (int p = 0; p < 2; ++p) {
                uint32_t off = ((brow + p*16)*KCP + bcol) * 2;
                uint32_t t4[4];
                ldsm4(t4, uBh + off);
                fBh[2*p][0] = t4[0]; fBh[2*p][1] = t4[1];
                fBh[2*p+1][0] = t4[2]; fBh[2*p+1][1] = t4[3];
                ldsm4(t4, uBl + off);
                fBl[2*p][0] = t4[0]; fBl[2*p][1] = t4[1];
                fBl[2*p+1][0] = t4[2]; fBl[2*p+1][1] = t4[3];
            }
#pragma unroll
            for (int mt = 0; mt < 4; ++mt)
#pragma unroll
                for (int nt = 0; nt < 4; ++nt) mma_bf16(acc[mt][nt], fAh[mt], fBh[nt]);
#pragma unroll
            for (int mt = 0; mt < 4; ++mt)
#pragma unroll
                for (int nt = 0; nt < 4; ++nt) mma_bf16(acc[mt][nt], fAh[mt], fBl[nt]);
#pragma unroll
            for (int mt = 0; mt < 4; ++mt)
#pragma unroll
                for (int nt = 0; nt < 4; ++nt) mma_bf16(acc[mt][nt], fAl[mt], fBh[nt]);
        }
        __syncthreads();
    }

    const int gid = lane >> 2;
    const int tig = lane & 3;
#pragma unroll
    for (int mt = 0; mt < 4; ++mt) {
        int mA = m0 + wm*64 + mt*16 + gid;
#pragma unroll
        for (int nt = 0; nt < 4; ++nt) {
            int n = n0 + wn*32 + nt*8 + tig*2;
            float2 bv = *(const float2*)&bias[n];
            float2 v0 = make_float2(acc[mt][nt][0] + bv.x, acc[mt][nt][1] + bv.y);
            float2 v1 = make_float2(acc[mt][nt][2] + bv.x, acc[mt][nt][3] + bv.y);
            *(float2*)&C[(size_t)mA*ldc + n]     = v0;
            *(float2*)&C[(size_t)(mA+8)*ldc + n] = v1;
        }
    }
}

// ---------------- persistent scan: 4 rows/warp, batch-split, race-free -------
#define SC_HB     0                          // 4 x 32768 staging
#define SC_SG     131072                     // 32768 partials
#define SC_ATTQ   (SC_SG + 32768)            // 2048
#define SC_SC     (SC_ATTQ + 2048)           // 512
#define SC_LSE    (SC_SC + 512)              // 16
#define SC_TOTAL  (SC_LSE + 16)

__global__ void __launch_bounds__(NTHR, 1)
scan_kernel(const float* __restrict__ ctx, const float* __restrict__ Whh,
            const float* __restrict__ Wih)
{
    extern __shared__ __align__(16) char dynsm[];
    float*  sgp    = (float*)(dynsm + SC_SG);
    float*  attq_s = (float*)(dynsm + SC_ATTQ);
    float*  sc_s   = (float*)(dynsm + SC_SC);
    float*  s_lse  = (float*)(dynsm + SC_LSE);
    const uint32_t smHb = smem_u32(dynsm);

    const int tid  = threadIdx.x;
    const int lane = tid & 31;
    const int w    = tid >> 5;
    const int wg   = w & 3;      // gate index (4 rows per warp)
    const int bh   = w >> 2;     // batch half
    const int blk  = blockIdx.x;
    const int j0   = blk * 4;
    const bool att_on = (blk & 1) == 0;
    const int cb   = blk >> 2;
    const int chalf = (blk >> 1) & 1;

    // persistent layer0 Whh weights
    ulonglong2 wA[4][4];
#pragma unroll
    for (int jj = 0; jj < 4; ++jj) {
        const ulonglong2* W = (const ulonglong2*)(Whh + (size_t)(wg*Hz + j0 + jj)*Hz);
#pragma unroll
        for (int i = 0; i < 4; ++i) wA[jj][i] = W[lane + 32*i];
    }
    // active layer1 weights (swapped per pass)
    ulonglong2 wB[4][4];
    auto loadB = [&](const float* Wsrc) {
#pragma unroll
        for (int jj = 0; jj < 4; ++jj) {
            const ulonglong2* W = (const ulonglong2*)(Wsrc + (size_t)(Gz + wg*Hz + j0 + jj)*Hz);
#pragma unroll
            for (int i = 0; i < 4; ++i) wB[jj][i] = W[lane + 32*i];
        }
    };
    loadB(Wih);

    auto stageH = [&](const float4* src, int buf) {
        uint32_t db = smHb + buf*32768 + tid*16;
#pragma unroll
        for (int i = 0; i < 8; ++i)
            CP_ASYNC16_CG(db + i*NTHR*16, src + tid + i*NTHR);
        CP_COMMIT();
    };

    // gate GEMV: 4 rows x 16 batches from one staged buffer
    auto gates4 = [&](int buf, int boff, int slotbase, ulonglong2 (&wt)[4][4]) {
        const ulonglong2* hb2 = (const ulonglong2*)(dynsm + buf*32768);
#pragma unroll 2
        for (int bl = 0; bl < 16; ++bl) {
            ulonglong2 h2[4];
#pragma unroll
            for (int i = 0; i < 4; ++i) h2[i] = hb2[bl*128 + lane + 32*i];
            unsigned long long a0 = 0ull, a1 = 0ull, a2 = 0ull, a3 = 0ull;
#pragma unroll
            for (int i = 0; i < 4; ++i) {
                ffma2(a0, h2[i].x, wt[0][i].x); ffma2(a0, h2[i].y, wt[0][i].y);
                ffma2(a1, h2[i].x, wt[1][i].x); ffma2(a1, h2[i].y, wt[1][i].y);
                ffma2(a2, h2[i].x, wt[2][i].x); ffma2(a2, h2[i].y, wt[2][i].y);
                ffma2(a3, h2[i].x, wt[3][i].x); ffma2(a3, h2[i].y, wt[3][i].y);
            }
            float s[4];
            float2 f0 = unpack2(a0); s[0] = f0.x + f0.y;
            float2 f1 = unpack2(a1); s[1] = f1.x + f1.y;
            float2 f2 = unpack2(a2); s[2] = f2.x + f2.y;
            float2 f3 = unpack2(a3); s[3] = f3.x + f3.y;
#pragma unroll
            for (int jj = 0; jj < 4; ++jj) {
                s[jj] += __shfl_xor_sync(0xffffffffu, s[jj], 16);
                s[jj] += __shfl_xor_sync(0xffffffffu, s[jj], 8);
            }
            if (lane < 8) {
                int b = boff + bl;
#pragma unroll
                for (int jj = 0; jj < 4; ++jj)
                    sgp[((wg*4 + jj)*32 + b)*16 + slotbase + lane] = s[jj];
            }
        }
    };

    unsigned nbar = 0;

    for (int t = 0; t < Tz; ++t) {
        const int p = t & 1;
        const float* h0p = d_h0buf + p*Bz*Hz;
        float*       h0n = d_h0buf + (p^1)*Bz*Hz;
        const float* h1p = d_h1buf + p*Bz*Hz;
        float*       h1n = d_h1buf + (p^1)*Bz*Hz;

        // ===== Phase A: layer0 gates (race-free: wait(0)+sync before ANY read) ==
        {
            const float4* Hp = (const float4*)h0p;
            stageH(Hp, 0);
            stageH(Hp + 2048, 1);
            CP_WAIT(0);
            __syncthreads();              // all threads' copies visible block-wide
            if (bh == 0) gates4(0, 0,  0, wA);
            else         gates4(1, 16, 0, wA);
            __syncthreads();
            if (tid < 128) {
                int b = tid >> 2, jj = tid & 3;
                int j = j0 + jj;
                const float* seed = d_g0ih + ((size_t)t*Bz + b)*Gz;
                float g4[4];
#pragma unroll
                for (int g = 0; g < 4; ++g) {
                    const float4* q = (const float4*)&sgp[((g*4 + jj)*32 + b)*16];
                    float4 q0 = q[0], q1 = q[1];
                    g4[g] = (q0.x + q0.y) + (q0.z + q0.w) + (q1.x + q1.y) + (q1.z + q1.w);
                }
                float gi = g4[0] + seed[j];
                float gf = g4[1] + seed[Hz + j];
                float gg = g4[2] + seed[2*Hz + j];
                float go = g4[3] + seed[3*Hz + j];
                int ci = b*Hz + j;
                float c = sigf(gf)*d_cstate[ci] + sigf(gi)*tanhf(gg);
                float h = sigf(go)*tanhf(c);
                d_cstate[ci] = c;
                __stcg(&h0n[ci], h);
                __stcg(&d_cat1[ci], h + d_x[((size_t)t*Bz + b)*Hz + j]);
            }
        }
        gbar(nbar, blk);

        // ===== Phase B: layer1 gates, 2 synced passes over 4 prefetched buffers ==
        {
            stageH((const float4*)d_cat1, 0);
            stageH((const float4*)d_cat1 + 2048, 1);
            stageH((const float4*)h1p, 2);
            stageH((const float4*)h1p + 2048, 3);
            CP_WAIT(2);
            __syncthreads();              // buffers 0,1 fully visible
            if (bh == 0) gates4(0, 0,  0, wB);   // cat1 x Wih1
            else         gates4(1, 16, 0, wB);
            loadB(Whh);                          // switch to Whh1
            CP_WAIT(0);
            __syncthreads();              // buffers 2,3 fully visible
            if (bh == 0) gates4(2, 0,  8, wB);   // h1 x Whh1
            else         gates4(3, 16, 8, wB);
            loadB(Wih);                          // restore for next step
            __syncthreads();
            if (tid < 128) {
                int b = tid >> 2, jj = tid & 3;
                int j = j0 + jj;
                float g4[4];
#pragma unroll
                for (int g = 0; g < 4; ++g) {
                    const float4* q = (const float4*)&sgp[((g*4 + jj)*32 + b)*16];
                    float4 q0 = q[0], q1 = q[1], q2 = q[2], q3 = q[3];
                    g4[g] = ((q0.x + q0.y) + (q0.z + q0.w)) + ((q1.x + q1.y) + (q1.z + q1.w))
                          + ((q2.x + q2.y) + (q2.z + q2.w)) + ((q3.x + q3.y) + (q3.z + q3.w));
                }
                float gi = g4[0] + d_bias1[j];
                float gf = g4[1] + d_bias1[Hz + j];
                float gg = g4[2] + d_bias1[2*Hz + j];
                float go = g4[3] + d_bias1[3*Hz + j];
                int ci = Bz*Hz + b*Hz + j;
                float c = sigf(gf)*d_cstate[ci] + sigf(gi)*tanhf(gg);
                float h = sigf(go)*tanhf(c);
                d_cstate[ci] = c;
                __stcg(&h1n[b*Hz + j], h);
                __stcg(&d_attq[b*Hz + j], h + __ldcg(&d_cat1[b*Hz + j]));
            }
        }
        gbar(nbar, blk);

        // ===== Phase C: attention (even blocks; batch cb, H-half chalf) =====
        if (att_on) {
            for (int i = tid; i < Hz; i += NTHR) attq_s[i] = __ldcg(&d_attq[cb*Hz + i]);
            __syncthreads();

            const float4* A4 = (const float4*)attq_s;
            for (int s = w*16; s < w*16 + 16; ++s) {
                const float4* C4 = (const float4*)(ctx + ((size_t)cb*Sz + s)*Hz);
                float acc = 0.f;
#pragma unroll
                for (int i = 0; i < 4; ++i) {
                    float4 c4 = C4[lane + 32*i];
                    float4 a4 = A4[lane + 32*i];
                    acc += c4.x*a4.x + c4.y*a4.y + c4.z*a4.z + c4.w*a4.w;
                }
#pragma unroll
                for (int o = 16; o; o >>= 1) acc += __shfl_xor_sync(0xffffffffu, acc, o);
                if (lane == 0) sc_s[s] = acc;
            }
            __syncthreads();

            if (w == 0) {
                float m = -1e30f;
                for (int s = lane; s < Sz; s += 32) m = fmaxf(m, sc_s[s]);
#pragma unroll
                for (int o = 16; o; o >>= 1) m = fmaxf(m, __shfl_xor_sync(0xffffffffu, m, o));
                float sm = 0.f;
                for (int s = lane; s < Sz; s += 32) sm += expf(sc_s[s] - m);
#pragma unroll
                for (int o = 16; o; o >>= 1) sm += __shfl_xor_sync(0xffffffffu, sm, o);
                if (lane == 0) *s_lse = m + logf(sm);
            }
            __syncthreads();
            float lse = *s_lse;

            int h = chalf*256 + tid;
            const float* cp = ctx + (size_t)cb*Sz*Hz + h;
            float acc = 0.f;
#pragma unroll 8
            for (int s = 0; s < Sz; ++s)
                acc += cp[(size_t)s*Hz] * (sc_s[s] - lse);
            size_t oi = ((size_t)cb*Tz + t)*Hz + h;
            __nv_bfloat16 hv = __float2bfloat16(acc);
            d_out_hi[oi] = hv;
            d_out_lo[oi] = __float2bfloat16(acc - __bfloat162float(hv));
            __syncthreads();
        }
    }
}

// ---------------- tail: hT, cT ----------------
__global__ void tail_kernel(float* __restrict__ out)
{
    int i = blockIdx.x * blockDim.x + threadIdx.x;
    const size_t base = (size_t)Bz*Tz*Vz;
    if (i < Bz*Hz)                 out[base + i] = d_h0buf[i];
    else if (i < 2*Bz*Hz)          out[base + i] = d_h1buf[i - Bz*Hz];
    else if (i < 4*Bz*Hz)          out[base + i] = d_cstate[i - 2*Bz*Hz];
}

// ---------------- launch ----------------
extern "C" void kernel_launch(void* const* d_in, const int* in_sizes, int n_in,
                              void* d_out, int out_size)
{
    const float* context = (const float*)d_in[0];
    const int*   dec     = (const int*)d_in[1];
    const float* h0      = (const float*)d_in[2];
    const float* c0      = (const float*)d_in[3];
    const float* emb     = (const float*)d_in[4];
    const float* Wih     = (const float*)d_in[5];
    const float* Whh     = (const float*)d_in[6];
    const float* bih     = (const float*)d_in[7];
    const float* bhh     = (const float*)d_in[8];
    const float* Wc      = (const float*)d_in[9];
    const float* bc      = (const float*)d_in[10];
    float* out = (float*)d_out;

    float *p_g0ih, *p_b0;
    __nv_bfloat16 *p_wch, *p_wcl, *p_oh, *p_ol, *p_xh, *p_xl, *p_wih, *p_wil;
    cudaGetSymbolAddress((void**)&p_g0ih, d_g0ih);
    cudaGetSymbolAddress((void**)&p_b0,   d_bias0);
    cudaGetSymbolAddress((void**)&p_wch,  d_Wc_hi);
    cudaGetSymbolAddress((void**)&p_wcl,  d_Wc_lo);
    cudaGetSymbolAddress((void**)&p_oh,   d_out_hi);
    cudaGetSymbolAddress((void**)&p_ol,   d_out_lo);
    cudaGetSymbolAddress((void**)&p_xh,   d_x_hi);
    cudaGetSymbolAddress((void**)&p_xl,   d_x_lo);
    cudaGetSymbolAddress((void**)&p_wih,  d_Wih0_hi);
    cudaGetSymbolAddress((void**)&p_wil,  d_Wih0_lo);

    const int SMEM_MMA = 2 * BUFB;   // 81920 -> 2 CTAs/SM
    cudaFuncSetAttribute(mma_gemm_kernel,
                         cudaFuncAttributeMaxDynamicSharedMemorySize, SMEM_MMA);
    cudaFuncSetAttribute(scan_kernel,
                         cudaFuncAttributeMaxDynamicSharedMemorySize, SC_TOTAL);

    init_kernel<<<(Tz*Bz*Hz + 255)/256, 256>>>(dec, emb, bih, bhh, h0, c0);

    {
        size_t n4 = (size_t)Vz*Hz/4;
        split_kernel<<<(unsigned)((n4 + 255)/256), 256>>>((const float4*)Wc, (uint2*)p_wch, (uint2*)p_wcl, n4);
        size_t m4 = (size_t)Gz*Hz/4;
        split_kernel<<<(unsigned)((m4 + 255)/256), 256>>>((const float4*)Wih, (uint2*)p_wih, (uint2*)p_wil, m4);
    }

    // g0ih = x @ Wih0^T + bias0
    {
        dim3 grid(Gz/128, (Tz*Bz)/128);
        mma_gemm_kernel<<<grid, 256, SMEM_MMA>>>(p_xh, p_xl, p_wih, p_wil, p_b0, p_g0ih, Gz);
    }

    // persistent scan
    scan_kernel<<<NBLK, NTHR, SC_TOTAL>>>(context, Whh, Wih);

    // logits = outs @ Wc^T + bc
    {
        dim3 grid(Vz/128, (Bz*Tz)/128);
        mma_gemm_kernel<<<grid, 256, SMEM_MMA>>>(p_oh, p_ol, p_wch, p_wcl, bc, out, Vz);
    }

    if ((long long)out_size >= (long long)Bz*Tz*Vz + 4LL*Bz*Hz) {
        tail_kernel<<<(4*Bz*Hz + 255)/256, 256>>>(out);
    }
}

// round 16
// speedup vs baseline: 1.1292x; 1.0076x over previous
#include <cuda_runtime.h>
#include <cuda_bf16.h>
#include <math.h>
#include <stdint.h>

#define Bz 32
#define Tz 64
#define Sz 128
#define Hz 512
#define Vz 32000
#define Gz 2048   // 4*H
#define NBLK 128
#define NTHR 256

// ---------------- device scratch ----------------
__device__ __align__(16) float d_x[Tz*Bz*Hz];
__device__ __align__(16) float d_g0ih[Tz*Bz*Gz];
__device__ __align__(16) float d_h0buf[2*Bz*Hz];
__device__ __align__(16) float d_h1buf[2*Bz*Hz];
__device__ __align__(16) float d_cstate[2*Bz*Hz];
__device__ __align__(16) float d_cat1[Bz*Hz];
__device__ __align__(16) float d_attq[Bz*Hz];
__device__ float d_bias0[Gz];
__device__ float d_bias1[Gz];
__device__ __align__(128) unsigned d_bar_cnt8[8*32];
// bf16 hi/lo splits
__device__ __align__(16) __nv_bfloat16 d_Wc_hi[(size_t)Vz*Hz];
__device__ __align__(16) __nv_bfloat16 d_Wc_lo[(size_t)Vz*Hz];
__device__ __align__(16) __nv_bfloat16 d_out_hi[Bz*Tz*Hz];
__device__ __align__(16) __nv_bfloat16 d_out_lo[Bz*Tz*Hz];
__device__ __align__(16) __nv_bfloat16 d_x_hi[Tz*Bz*Hz];
__device__ __align__(16) __nv_bfloat16 d_x_lo[Tz*Bz*Hz];
__device__ __align__(16) __nv_bfloat16 d_Wih0_hi[Gz*Hz];
__device__ __align__(16) __nv_bfloat16 d_Wih0_lo[Gz*Hz];

__device__ __forceinline__ float sigf(float x) { return 1.f / (1.f + expf(-x)); }

// ---------------- packed f32x2 helpers ----------------
__device__ __forceinline__ void ffma2(unsigned long long &d,
                                      unsigned long long a,
                                      unsigned long long b)
{
    asm("fma.rn.f32x2 %0, %1, %2, %0;" : "+l"(d) : "l"(a), "l"(b));
}
__device__ __forceinline__ float2 unpack2(unsigned long long v)
{
    unsigned lo, hi;
    asm("mov.b64 {%0, %1}, %2;" : "=r"(lo), "=r"(hi) : "l"(v));
    return make_float2(__uint_as_float(lo), __uint_as_float(hi));
}

// ---------------- mma.sync / ldmatrix / cp.async helpers ----------------
__device__ __forceinline__ uint32_t smem_u32(const void* p) {
    uint32_t a;
    asm("{ .reg .u64 t; cvta.to.shared.u64 t, %1; cvt.u32.u64 %0, t; }" : "=r"(a) : "l"(p));
    return a;
}
__device__ __forceinline__ void ldsm4(uint32_t (&r)[4], uint32_t addr)
{
    asm volatile("ldmatrix.sync.aligned.m8n8.x4.shared.b16 {%0,%1,%2,%3}, [%4];"
                 : "=r"(r[0]), "=r"(r[1]), "=r"(r[2]), "=r"(r[3]) : "r"(addr));
}
__device__ __forceinline__ void mma_bf16(float (&c)[4], const uint32_t (&a)[4],
                                         const uint32_t* b)
{
    asm volatile(
        "mma.sync.aligned.m16n8k16.row.col.f32.bf16.bf16.f32 "
        "{%0,%1,%2,%3}, {%4,%5,%6,%7}, {%8,%9}, {%0,%1,%2,%3};"
        : "+f"(c[0]), "+f"(c[1]), "+f"(c[2]), "+f"(c[3])
        : "r"(a[0]), "r"(a[1]), "r"(a[2]), "r"(a[3]), "r"(b[0]), "r"(b[1]));
}
#define CP_ASYNC16_CG(dst, src) \
    asm volatile("cp.async.cg.shared.global [%0], [%1], 16;" :: "r"(dst), "l"(src))
#define CP_COMMIT() asm volatile("cp.async.commit_group;" ::: "memory")
#define CP_WAIT(n)  asm volatile("cp.async.wait_group %0;" :: "n"(n) : "memory")

// ---------------- grid barrier: 8 distributed counters ----------------
__device__ __forceinline__ void gbar(unsigned &nbar, int blk)
{
    nbar++;
    __syncthreads();
    if (threadIdx.x == 0) {
        __threadfence();
        atomicAdd(&d_bar_cnt8[(blk & 7) * 32], 1u);
        const unsigned target = nbar * (NBLK / 8);
        for (;;) {
            bool done = true;
#pragma unroll
            for (int i = 0; i < 8; ++i)
                done &= (*(volatile unsigned*)&d_bar_cnt8[i * 32] >= target);
            if (done) break;
        }
    }
    __syncthreads();
}

// ---------------- fused init ----------------
__global__ void init_kernel(const int* __restrict__ ids32, const float* __restrict__ emb,
                            const float* __restrict__ bih, const float* __restrict__ bhh,
                            const float* __restrict__ h0, const float* __restrict__ c0)
{
    int i = blockIdx.x * blockDim.x + threadIdx.x;
    if (i < 8) d_bar_cnt8[i * 32] = 0u;
    if (i < Gz) {
        d_bias0[i] = bih[i] + bhh[i];
        d_bias1[i] = bih[Gz + i] + bhh[Gz + i];
    }
    if (i < Bz*Hz) {
        d_h0buf[i] = h0[i];
        d_h1buf[i] = h0[Bz*Hz + i];
    }
    if (i < 2*Bz*Hz) d_cstate[i] = c0[i];
    if (i < Tz*Bz*Hz) {
        bool is64 = (ids32[1] == 0) && (ids32[3] == 0) && (ids32[5] == 0);
        int h = i % Hz;
        int tb = i / Hz;
        int b = tb % Bz;
        int t = tb / Bz;
        int idx = b*Tz + t;
        int id = is64 ? ids32[2*idx] : ids32[idx];
        if (id < 0 || id >= Vz) id = 0;
        float v = (id == 0) ? 0.f : emb[(size_t)id*Hz + h];
        d_x[i] = v;
        __nv_bfloat16 hv = __float2bfloat16(v);
        d_x_hi[i] = hv;
        d_x_lo[i] = __float2bfloat16(v - __bfloat162float(hv));
    }
}

// ---------------- hi/lo bf16 split (vectorized) ----------------
__global__ void split_kernel(const float4* __restrict__ src,
                             uint2* __restrict__ hi,
                             uint2* __restrict__ lo, size_t n4)
{
    size_t i = (size_t)blockIdx.x * blockDim.x + threadIdx.x;
    if (i >= n4) return;
    float4 v = src[i];
    __nv_bfloat16 hx = __float2bfloat16(v.x);
    __nv_bfloat16 hy = __float2bfloat16(v.y);
    __nv_bfloat16 hz = __float2bfloat16(v.z);
    __nv_bfloat16 hw = __float2bfloat16(v.w);
    __nv_bfloat16 lx = __float2bfloat16(v.x - __bfloat162float(hx));
    __nv_bfloat16 ly = __float2bfloat16(v.y - __bfloat162float(hy));
    __nv_bfloat16 lz = __float2bfloat16(v.z - __bfloat162float(hz));
    __nv_bfloat16 lw = __float2bfloat16(v.w - __bfloat162float(hw));
    uint2 ho, lu;
    ho.x = (uint32_t)__bfloat16_as_ushort(hx) | ((uint32_t)__bfloat16_as_ushort(hy) << 16);
    ho.y = (uint32_t)__bfloat16_as_ushort(hz) | ((uint32_t)__bfloat16_as_ushort(hw) << 16);
    lu.x = (uint32_t)__bfloat16_as_ushort(lx) | ((uint32_t)__bfloat16_as_ushort(ly) << 16);
    lu.y = (uint32_t)__bfloat16_as_ushort(lz) | ((uint32_t)__bfloat16_as_ushort(lw) << 16);
    hi[i] = ho;
    lo[i] = lu;
}

// ---------------- bf16-split mma GEMM (8 warps, 64x32 warp tile) --------------
#define KC    32
#define KCP   40
#define ARRB  (128*KCP*2)                // 10240
#define BUFB  (4*ARRB)                   // 40960

__global__ void __launch_bounds__(256, 2)
mma_gemm_kernel(const __nv_bfloat16* __restrict__ Ahi, const __nv_bfloat16* __restrict__ Alo,
                const __nv_bfloat16* __restrict__ Bhi, const __nv_bfloat16* __restrict__ Blo,
                const float* __restrict__ bias, float* __restrict__ C, int ldc)
{
    extern __shared__ __align__(16) char sm_raw[];

    const int tid  = threadIdx.x;
    const int lane = tid & 31;
    const int wid  = tid >> 5;
    const int wm   = wid >> 2;
    const int wn   = wid & 3;
    const int n0   = blockIdx.x * 128;
    const int m0   = blockIdx.y * 128;

    float acc[4][4][4];
#pragma unroll
    for (int i = 0; i < 4; ++i)
#pragma unroll
        for (int j = 0; j < 4; ++j)
#pragma unroll
            for (int v = 0; v < 4; ++v) acc[i][j][v] = 0.f;

    const int gr = tid >> 1;
    const int gs = (tid & 1) * 2;

    const uint32_t smBase = smem_u32(sm_raw);

    auto stage = [&](int c, int buf) {
        const int k0 = c * KC;
        uint32_t db = smBase + buf*BUFB + gr*(KCP*2) + gs*16;
        const __nv_bfloat16* pAh = Ahi + (size_t)(m0 + gr)*Hz + k0 + gs*8;
        const __nv_bfloat16* pAl = Alo + (size_t)(m0 + gr)*Hz + k0 + gs*8;
        const __nv_bfloat16* pBh = Bhi + (size_t)(n0 + gr)*Hz + k0 + gs*8;
        const __nv_bfloat16* pBl = Blo + (size_t)(n0 + gr)*Hz + k0 + gs*8;
#pragma unroll
        for (int i = 0; i < 2; ++i) {
            CP_ASYNC16_CG(db + i*16 + 0*ARRB, pAh + i*8);
            CP_ASYNC16_CG(db + i*16 + 1*ARRB, pAl + i*8);
            CP_ASYNC16_CG(db + i*16 + 2*ARRB, pBh + i*8);
            CP_ASYNC16_CG(db + i*16 + 3*ARRB, pBl + i*8);
        }
        CP_COMMIT();
    };

    const int NCHUNK = Hz / KC;   // 16
    stage(0, 0);

    for (int c = 0; c < NCHUNK; ++c) {
        if (c + 1 < NCHUNK) { stage(c + 1, (c + 1) & 1); CP_WAIT(1); }
        else                { CP_WAIT(0); }
        __syncthreads();

        const uint32_t bb  = smBase + (c & 1)*BUFB;
        const uint32_t uAh = bb;
        const uint32_t uAl = bb + 1*ARRB;
        const uint32_t uBh = bb + 2*ARRB;
        const uint32_t uBl = bb + 3*ARRB;

#pragma unroll
        for (int ks = 0; ks < KC/16; ++ks) {
            uint32_t fAh[4][4], fAl[4][4], fBh[4][2], fBl[4][2];
            const int arow = wm*64 + (lane & 15);
            const int acol = ks*16 + ((lane >> 4) << 3);
#pragma unroll
            for (int mt = 0; mt < 4; ++mt) {
                uint32_t off = ((arow + mt*16)*KCP + acol) * 2;
                ldsm4(fAh[mt], uAh + off);
                ldsm4(fAl[mt], uAl + off);
            }
            const int brow = wn*32 + (lane & 7) + ((lane >> 4) << 3);
            const int bcol = ks*16 + (lane & 8);
#pragma unroll
            for (int p = 0; p < 2; ++p) {
                uint32_t off = ((brow + p*16)*KCP + bcol) * 2;
                uint32_t t4[4];
                ldsm4(t4, uBh + off);
                fBh[2*p][0] = t4[0]; fBh[2*p][1] = t4[1];
                fBh[2*p+1][0] = t4[2]; fBh[2*p+1][1] = t4[3];
                ldsm4(t4, uBl + off);
                fBl[2*p][0] = t4[0]; fBl[2*p][1] = t4[1];
                fBl[2*p+1][0] = t4[2]; fBl[2*p+1][1] = t4[3];
            }
#pragma unroll
            for (int mt = 0; mt < 4; ++mt)
#pragma unroll
                for (int nt = 0; nt < 4; ++nt) mma_bf16(acc[mt][nt], fAh[mt], fBh[nt]);
#pragma unroll
            for (int mt = 0; mt < 4; ++mt)
#pragma unroll
                for (int nt = 0; nt < 4; ++nt) mma_bf16(acc[mt][nt], fAh[mt], fBl[nt]);
#pragma unroll
            for (int mt = 0; mt < 4; ++mt)
#pragma unroll
                for (int nt = 0; nt < 4; ++nt) mma_bf16(acc[mt][nt], fAl[mt], fBh[nt]);
        }
        __syncthreads();
    }

    const int gid = lane >> 2;
    const int tig = lane & 3;
#pragma unroll
    for (int mt = 0; mt < 4; ++mt) {
        int mA = m0 + wm*64 + mt*16 + gid;
#pragma unroll
        for (int nt = 0; nt < 4; ++nt) {
            int n = n0 + wn*32 + nt*8 + tig*2;
            float2 bv = *(const float2*)&bias[n];
            float2 v0 = make_float2(acc[mt][nt][0] + bv.x, acc[mt][nt][1] + bv.y);
            float2 v1 = make_float2(acc[mt][nt][2] + bv.x, acc[mt][nt][3] + bv.y);
            *(float2*)&C[(size_t)mA*ldc + n]     = v0;
            *(float2*)&C[(size_t)(mA+8)*ldc + n] = v1;
        }
    }
}

// ---------------- persistent scan: prefetched staging, race-free -------------
// Per-step cp.async groups (in commit order): A1,A2 (next h0), Bh1,Bh2 (next h1),
// Bc1,Bc2 (cat1). Waits: A -> WAIT(2); B pass1 (h1) -> WAIT(2); B pass2 -> WAIT(0).
#define SC_HB     0                          // 4 x 32768 staging
#define SC_SG     131072                     // 32768 partials
#define SC_ATTQ   (SC_SG + 32768)            // 2048
#define SC_SC     (SC_ATTQ + 2048)           // 512
#define SC_LSE    (SC_SC + 512)              // 16
#define SC_TOTAL  (SC_LSE + 16)

__global__ void __launch_bounds__(NTHR, 1)
scan_kernel(const float* __restrict__ ctx, const float* __restrict__ Whh,
            const float* __restrict__ Wih)
{
    extern __shared__ __align__(16) char dynsm[];
    float*  sgp    = (float*)(dynsm + SC_SG);
    float*  attq_s = (float*)(dynsm + SC_ATTQ);
    float*  sc_s   = (float*)(dynsm + SC_SC);
    float*  s_lse  = (float*)(dynsm + SC_LSE);
    const uint32_t smHb = smem_u32(dynsm);

    const int tid  = threadIdx.x;
    const int lane = tid & 31;
    const int w    = tid >> 5;
    const int wg   = w & 3;      // gate index (4 rows per warp)
    const int bh   = w >> 2;     // batch half
    const int blk  = blockIdx.x;
    const int j0   = blk * 4;
    const bool att_on = (blk & 1) == 0;
    const int cb   = blk >> 2;
    const int chalf = (blk >> 1) & 1;

    // persistent layer0 Whh weights
    ulonglong2 wA[4][4];
#pragma unroll
    for (int jj = 0; jj < 4; ++jj) {
        const ulonglong2* W = (const ulonglong2*)(Whh + (size_t)(wg*Hz + j0 + jj)*Hz);
#pragma unroll
        for (int i = 0; i < 4; ++i) wA[jj][i] = W[lane + 32*i];
    }
    // active layer1 weights (pass1: Whh1, pass2: Wih1)
    ulonglong2 wB[4][4];
    auto loadB = [&](const float* Wsrc) {
#pragma unroll
        for (int jj = 0; jj < 4; ++jj) {
            const ulonglong2* W = (const ulonglong2*)(Wsrc + (size_t)(Gz + wg*Hz + j0 + jj)*Hz);
#pragma unroll
            for (int i = 0; i < 4; ++i) wB[jj][i] = W[lane + 32*i];
        }
    };
    loadB(Whh);   // pass1 weights

    auto stageH = [&](const float4* src, int buf) {
        uint32_t db = smHb + buf*32768 + tid*16;
#pragma unroll
        for (int i = 0; i < 8; ++i)
            CP_ASYNC16_CG(db + i*NTHR*16, src + tid + i*NTHR);
        CP_COMMIT();
    };

    // gate GEMV: 4 rows x 16 batches from one staged buffer
    auto gates4 = [&](int buf, int boff, int slotbase, ulonglong2 (&wt)[4][4]) {
        const ulonglong2* hb2 = (const ulonglong2*)(dynsm + buf*32768);
#pragma unroll 2
        for (int bl = 0; bl < 16; ++bl) {
            ulonglong2 h2[4];
#pragma unroll
            for (int i = 0; i < 4; ++i) h2[i] = hb2[bl*128 + lane + 32*i];
            unsigned long long a0 = 0ull, a1 = 0ull, a2 = 0ull, a3 = 0ull;
#pragma unroll
            for (int i = 0; i < 4; ++i) {
                ffma2(a0, h2[i].x, wt[0][i].x); ffma2(a0, h2[i].y, wt[0][i].y);
                ffma2(a1, h2[i].x, wt[1][i].x); ffma2(a1, h2[i].y, wt[1][i].y);
                ffma2(a2, h2[i].x, wt[2][i].x); ffma2(a2, h2[i].y, wt[2][i].y);
                ffma2(a3, h2[i].x, wt[3][i].x); ffma2(a3, h2[i].y, wt[3][i].y);
            }
            float s[4];
            float2 f0 = unpack2(a0); s[0] = f0.x + f0.y;
            float2 f1 = unpack2(a1); s[1] = f1.x + f1.y;
            float2 f2 = unpack2(a2); s[2] = f2.x + f2.y;
            float2 f3 = unpack2(a3); s[3] = f3.x + f3.y;
#pragma unroll
            for (int jj = 0; jj < 4; ++jj) {
                s[jj] += __shfl_xor_sync(0xffffffffu, s[jj], 16);
                s[jj] += __shfl_xor_sync(0xffffffffu, s[jj], 8);
            }
            if (lane < 8) {
                int b = boff + bl;
#pragma unroll
                for (int jj = 0; jj < 4; ++jj)
                    sgp[((wg*4 + jj)*32 + b)*16 + slotbase + lane] = s[jj];
            }
        }
    };

    unsigned nbar = 0;

    // ---- prologue prefetch for t=0: h0 -> bufs 0,1 ; h1 -> bufs 2,3 ----
    {
        const float4* H0p = (const float4*)(d_h0buf);
        const float4* H1p = (const float4*)(d_h1buf);
        stageH(H0p, 0);        // group A1
        stageH(H0p + 2048, 1); // group A2
        stageH(H1p, 2);        // group Bh1
        stageH(H1p + 2048, 3); // group Bh2
    }

    for (int t = 0; t < Tz; ++t) {
        const int p = t & 1;
        float*       h0n = d_h0buf + (p^1)*Bz*Hz;
        float*       h1n = d_h1buf + (p^1)*Bz*Hz;

        // ===== Phase A: layer0 gates (h0 prefetched into bufs 0,1) =====
        {
            CP_WAIT(2);              // A1,A2 done (Bh1,Bh2 may pend)
            __syncthreads();
            if (bh == 0) gates4(0, 0,  0, wA);
            else         gates4(1, 16, 0, wA);
            __syncthreads();
            if (tid < 128) {
                int b = tid >> 2, jj = tid & 3;
                int j = j0 + jj;
                const float* seed = d_g0ih + ((size_t)t*Bz + b)*Gz;
                float g4[4];
#pragma unroll
                for (int g = 0; g < 4; ++g) {
                    const float4* q = (const float4*)&sgp[((g*4 + jj)*32 + b)*16];
                    float4 q0 = q[0], q1 = q[1];
                    g4[g] = (q0.x + q0.y) + (q0.z + q0.w) + (q1.x + q1.y) + (q1.z + q1.w);
                }
                float gi = g4[0] + seed[j];
                float gf = g4[1] + seed[Hz + j];
                float gg = g4[2] + seed[2*Hz + j];
                float go = g4[3] + seed[3*Hz + j];
                int ci = b*Hz + j;
                float c = sigf(gf)*d_cstate[ci] + sigf(gi)*tanhf(gg);
                float h = sigf(go)*tanhf(c);
                d_cstate[ci] = c;
                __stcg(&h0n[ci], h);
                __stcg(&d_cat1[ci], h + d_x[((size_t)t*Bz + b)*Hz + j]);
            }
        }
        gbar(nbar, blk);

        // ===== Phase B: pass1 h1 x Whh1 (prefetched bufs 2,3), pass2 cat1 x Wih1
        {
            stageH((const float4*)d_cat1, 0);        // group Bc1
            stageH((const float4*)d_cat1 + 2048, 1); // group Bc2
            CP_WAIT(2);              // Bh1,Bh2 done (Bc1,Bc2 may pend)
            __syncthreads();
            if (bh == 0) gates4(2, 0,  8, wB);       // h1 x Whh1 -> slots 8-15
            else         gates4(3, 16, 8, wB);
            loadB(Wih);                              // switch to Wih1
            CP_WAIT(0);
            __syncthreads();
            if (bh == 0) gates4(0, 0,  0, wB);       // cat1 x Wih1 -> slots 0-7
            else         gates4(1, 16, 0, wB);
            loadB(Whh);                              // restore pass1 weights
            __syncthreads();
            if (tid < 128) {
                int b = tid >> 2, jj = tid & 3;
                int j = j0 + jj;
                float g4[4];
#pragma unroll
                for (int g = 0; g < 4; ++g) {
                    const float4* q = (const float4*)&sgp[((g*4 + jj)*32 + b)*16];
                    float4 q0 = q[0], q1 = q[1], q2 = q[2], q3 = q[3];
                    g4[g] = ((q0.x + q0.y) + (q0.z + q0.w)) + ((q1.x + q1.y) + (q1.z + q1.w))
                          + ((q2.x + q2.y) + (q2.z + q2.w)) + ((q3.x + q3.y) + (q3.z + q3.w));
                }
                float gi = g4[0] + d_bias1[j];
                float gf = g4[1] + d_bias1[Hz + j];
                float gg = g4[2] + d_bias1[2*Hz + j];
                float go = g4[3] + d_bias1[3*Hz + j];
                int ci = Bz*Hz + b*Hz + j;
                float c = sigf(gf)*d_cstate[ci] + sigf(gi)*tanhf(gg);
                float h = sigf(go)*tanhf(c);
                d_cstate[ci] = c;
                __stcg(&h1n[b*Hz + j], h);
                __stcg(&d_attq[b*Hz + j], h + __ldcg(&d_cat1[b*Hz + j]));
            }
        }
        gbar(nbar, blk);

        // ===== prefetch next step's A (h0n) and B-h1 (h1n) — both final now ====
        if (t + 1 < Tz) {
            const float4* H0n = (const float4*)h0n;
            const float4* H1n = (const float4*)h1n;
            stageH(H0n, 0);         // group A1'
            stageH(H0n + 2048, 1);  // group A2'
            stageH(H1n, 2);         // group Bh1'
            stageH(H1n + 2048, 3);  // group Bh2'
        }

        // ===== Phase C: attention (even blocks; batch cb, H-half chalf) =====
        if (att_on) {
            for (int i = tid; i < Hz; i += NTHR) attq_s[i] = __ldcg(&d_attq[cb*Hz + i]);
            __syncthreads();

            const float4* A4 = (const float4*)attq_s;
            for (int s = w*16; s < w*16 + 16; ++s) {
                const float4* C4 = (const float4*)(ctx + ((size_t)cb*Sz + s)*Hz);
                float acc = 0.f;
#pragma unroll
                for (int i = 0; i < 4; ++i) {
                    float4 c4 = C4[lane + 32*i];
                    float4 a4 = A4[lane + 32*i];
                    acc += c4.x*a4.x + c4.y*a4.y + c4.z*a4.z + c4.w*a4.w;
                }
#pragma unroll
                for (int o = 16; o; o >>= 1) acc += __shfl_xor_sync(0xffffffffu, acc, o);
                if (lane == 0) sc_s[s] = acc;
            }
            __syncthreads();

            if (w == 0) {
                float m = -1e30f;
                for (int s = lane; s < Sz; s += 32) m = fmaxf(m, sc_s[s]);
#pragma unroll
                for (int o = 16; o; o >>= 1) m = fmaxf(m, __shfl_xor_sync(0xffffffffu, m, o));
                float sm = 0.f;
                for (int s = lane; s < Sz; s += 32) sm += expf(sc_s[s] - m);
#pragma unroll
                for (int o = 16; o; o >>= 1) sm += __shfl_xor_sync(0xffffffffu, sm, o);
                if (lane == 0) *s_lse = m + logf(sm);
            }
            __syncthreads();
            float lse = *s_lse;

            int h = chalf*256 + tid;
            const float* cp = ctx + (size_t)cb*Sz*Hz + h;
            float acc = 0.f;
#pragma unroll 8
            for (int s = 0; s < Sz; ++s)
                acc += cp[(size_t)s*Hz] * (sc_s[s] - lse);
            size_t oi = ((size_t)cb*Tz + t)*Hz + h;
            __nv_bfloat16 hv = __float2bfloat16(acc);
            d_out_hi[oi] = hv;
            d_out_lo[oi] = __float2bfloat16(acc - __bfloat162float(hv));
            __syncthreads();
        }
    }
}

// ---------------- tail: hT, cT ----------------
__global__ void tail_kernel(float* __restrict__ out)
{
    int i = blockIdx.x * blockDim.x + threadIdx.x;
    const size_t base = (size_t)Bz*Tz*Vz;
    if (i < Bz*Hz)                 out[base + i] = d_h0buf[i];
    else if (i < 2*Bz*Hz)          out[base + i] = d_h1buf[i - Bz*Hz];
    else if (i < 4*Bz*Hz)          out[base + i] = d_cstate[i - 2*Bz*Hz];
}

// ---------------- launch ----------------
extern "C" void kernel_launch(void* const* d_in, const int* in_sizes, int n_in,
                              void* d_out, int out_size)
{
    const float* context = (const float*)d_in[0];
    const int*   dec     = (const int*)d_in[1];
    const float* h0      = (const float*)d_in[2];
    const float* c0      = (const float*)d_in[3];
    const float* emb     = (const float*)d_in[4];
    const float* Wih     = (const float*)d_in[5];
    const float* Whh     = (const float*)d_in[6];
    const float* bih     = (const float*)d_in[7];
    const float* bhh     = (const float*)d_in[8];
    const float* Wc      = (const float*)d_in[9];
    const float* bc      = (const float*)d_in[10];
    float* out = (float*)d_out;

    float *p_g0ih, *p_b0;
    __nv_bfloat16 *p_wch, *p_wcl, *p_oh, *p_ol, *p_xh, *p_xl, *p_wih, *p_wil;
    cudaGetSymbolAddress((void**)&p_g0ih, d_g0ih);
    cudaGetSymbolAddress((void**)&p_b0,   d_bias0);
    cudaGetSymbolAddress((void**)&p_wch,  d_Wc_hi);
    cudaGetSymbolAddress((void**)&p_wcl,  d_Wc_lo);
    cudaGetSymbolAddress((void**)&p_oh,   d_out_hi);
    cudaGetSymbolAddress((void**)&p_ol,   d_out_lo);
    cudaGetSymbolAddress((void**)&p_xh,   d_x_hi);
    cudaGetSymbolAddress((void**)&p_xl,   d_x_lo);
    cudaGetSymbolAddress((void**)&p_wih,  d_Wih0_hi);
    cudaGetSymbolAddress((void**)&p_wil,  d_Wih0_lo);

    const int SMEM_MMA = 2 * BUFB;   // 81920 -> 2 CTAs/SM
    cudaFuncSetAttribute(mma_gemm_kernel,
                         cudaFuncAttributeMaxDynamicSharedMemorySize, SMEM_MMA);
    cudaFuncSetAttribute(scan_kernel,
                         cudaFuncAttributeMaxDynamicSharedMemorySize, SC_TOTAL);

    init_kernel<<<(Tz*Bz*Hz + 255)/256, 256>>>(dec, emb, bih, bhh, h0, c0);

    {
        size_t n4 = (size_t)Vz*Hz/4;
        split_kernel<<<(unsigned)((n4 + 255)/256), 256>>>((const float4*)Wc, (uint2*)p_wch, (uint2*)p_wcl, n4);
        size_t m4 = (size_t)Gz*Hz/4;
        split_kernel<<<(unsigned)((m4 + 255)/256), 256>>>((const float4*)Wih, (uint2*)p_wih, (uint2*)p_wil, m4);
    }

    // g0ih = x @ Wih0^T + bias0
    {
        dim3 grid(Gz/128, (Tz*Bz)/128);
        mma_gemm_kernel<<<grid, 256, SMEM_MMA>>>(p_xh, p_xl, p_wih, p_wil, p_b0, p_g0ih, Gz);
    }

    // persistent scan
    scan_kernel<<<NBLK, NTHR, SC_TOTAL>>>(context, Whh, Wih);

    // logits = outs @ Wc^T + bc
    {
        dim3 grid(Vz/128, (Bz*Tz)/128);
        mma_gemm_kernel<<<grid, 256, SMEM_MMA>>>(p_oh, p_ol, p_wch, p_wcl, bc, out, Vz);
    }

    if ((long long)out_size >= (long long)Bz*Tz*Vz + 4LL*Bz*Hz) {
        tail_kernel<<<(4*Bz*Hz + 255)/256, 256>>>(out);
    }
}

// round 17
// speedup vs baseline: 1.1648x; 1.0316x over previous
#include <cuda_runtime.h>
#include <cuda_bf16.h>
#include <math.h>
#include <stdint.h>

#define Bz 32
#define Tz 64
#define Sz 128
#define Hz 512
#define Vz 32000
#define Gz 2048   // 4*H
#define NBLK 128
#define NTHR 256

// ---------------- device scratch ----------------
__device__ __align__(16) float d_x[Tz*Bz*Hz];
__device__ __align__(16) float d_g0ih[Tz*Bz*Gz];
__device__ __align__(16) float d_h0buf[2*Bz*Hz];
__device__ __align__(16) float d_h1buf[2*Bz*Hz];
__device__ __align__(16) float d_cstate[2*Bz*Hz];
__device__ __align__(16) float d_cat1[Bz*Hz];
__device__ __align__(16) float d_attq[Bz*Hz];
__device__ float d_bias0[Gz];
__device__ float d_bias1[Gz];
__device__ __align__(128) unsigned d_bar_cnt8[8*32];
// bf16 hi/lo splits
__device__ __align__(16) __nv_bfloat16 d_Wc_hi[(size_t)Vz*Hz];
__device__ __align__(16) __nv_bfloat16 d_Wc_lo[(size_t)Vz*Hz];
__device__ __align__(16) __nv_bfloat16 d_out_hi[Bz*Tz*Hz];
__device__ __align__(16) __nv_bfloat16 d_out_lo[Bz*Tz*Hz];
__device__ __align__(16) __nv_bfloat16 d_x_hi[Tz*Bz*Hz];
__device__ __align__(16) __nv_bfloat16 d_x_lo[Tz*Bz*Hz];
__device__ __align__(16) __nv_bfloat16 d_Wih0_hi[Gz*Hz];
__device__ __align__(16) __nv_bfloat16 d_Wih0_lo[Gz*Hz];

__device__ __forceinline__ float sigf(float x) { return 1.f / (1.f + expf(-x)); }

// ---------------- packed f32x2 helpers ----------------
__device__ __forceinline__ void ffma2(unsigned long long &d,
                                      unsigned long long a,
                                      unsigned long long b)
{
    asm("fma.rn.f32x2 %0, %1, %2, %0;" : "+l"(d) : "l"(a), "l"(b));
}
__device__ __forceinline__ float2 unpack2(unsigned long long v)
{
    unsigned lo, hi;
    asm("mov.b64 {%0, %1}, %2;" : "=r"(lo), "=r"(hi) : "l"(v));
    return make_float2(__uint_as_float(lo), __uint_as_float(hi));
}

// ---------------- mma.sync / ldmatrix / cp.async helpers ----------------
__device__ __forceinline__ uint32_t smem_u32(const void* p) {
    uint32_t a;
    asm("{ .reg .u64 t; cvta.to.shared.u64 t, %1; cvt.u32.u64 %0, t; }" : "=r"(a) : "l"(p));
    return a;
}
__device__ __forceinline__ void ldsm4(uint32_t (&r)[4], uint32_t addr)
{
    asm volatile("ldmatrix.sync.aligned.m8n8.x4.shared.b16 {%0,%1,%2,%3}, [%4];"
                 : "=r"(r[0]), "=r"(r[1]), "=r"(r[2]), "=r"(r[3]) : "r"(addr));
}
__device__ __forceinline__ void mma_bf16(float (&c)[4], const uint32_t (&a)[4],
                                         const uint32_t* b)
{
    asm volatile(
        "mma.sync.aligned.m16n8k16.row.col.f32.bf16.bf16.f32 "
        "{%0,%1,%2,%3}, {%4,%5,%6,%7}, {%8,%9}, {%0,%1,%2,%3};"
        : "+f"(c[0]), "+f"(c[1]), "+f"(c[2]), "+f"(c[3])
        : "r"(a[0]), "r"(a[1]), "r"(a[2]), "r"(a[3]), "r"(b[0]), "r"(b[1]));
}
#define CP_ASYNC16_CG(dst, src) \
    asm volatile("cp.async.cg.shared.global [%0], [%1], 16;" :: "r"(dst), "l"(src))
#define CP_COMMIT() asm volatile("cp.async.commit_group;" ::: "memory")
#define CP_WAIT(n)  asm volatile("cp.async.wait_group %0;" :: "n"(n) : "memory")

// ---------------- grid barrier: 8 distributed counters ----------------
__device__ __forceinline__ void gbar(unsigned &nbar, int blk)
{
    nbar++;
    __syncthreads();
    if (threadIdx.x == 0) {
        __threadfence();
        atomicAdd(&d_bar_cnt8[(blk & 7) * 32], 1u);
        const unsigned target = nbar * (NBLK / 8);
        for (;;) {
            bool done = true;
#pragma unroll
            for (int i = 0; i < 8; ++i)
                done &= (*(volatile unsigned*)&d_bar_cnt8[i * 32] >= target);
            if (done) break;
        }
    }
    __syncthreads();
}

// ---------------- fused init ----------------
__global__ void init_kernel(const int* __restrict__ ids32, const float* __restrict__ emb,
                            const float* __restrict__ bih, const float* __restrict__ bhh,
                            const float* __restrict__ h0, const float* __restrict__ c0)
{
    int i = blockIdx.x * blockDim.x + threadIdx.x;
    if (i < 8) d_bar_cnt8[i * 32] = 0u;
    if (i < Gz) {
        d_bias0[i] = bih[i] + bhh[i];
        d_bias1[i] = bih[Gz + i] + bhh[Gz + i];
    }
    if (i < Bz*Hz) {
        d_h0buf[i] = h0[i];
        d_h1buf[i] = h0[Bz*Hz + i];
    }
    if (i < 2*Bz*Hz) d_cstate[i] = c0[i];
    if (i < Tz*Bz*Hz) {
        bool is64 = (ids32[1] == 0) && (ids32[3] == 0) && (ids32[5] == 0);
        int h = i % Hz;
        int tb = i / Hz;
        int b = tb % Bz;
        int t = tb / Bz;
        int idx = b*Tz + t;
        int id = is64 ? ids32[2*idx] : ids32[idx];
        if (id < 0 || id >= Vz) id = 0;
        float v = (id == 0) ? 0.f : emb[(size_t)id*Hz + h];
        d_x[i] = v;
        __nv_bfloat16 hv = __float2bfloat16(v);
        d_x_hi[i] = hv;
        d_x_lo[i] = __float2bfloat16(v - __bfloat162float(hv));
    }
}

// ---------------- hi/lo bf16 split (vectorized) ----------------
__global__ void split_kernel(const float4* __restrict__ src,
                             uint2* __restrict__ hi,
                             uint2* __restrict__ lo, size_t n4)
{
    size_t i = (size_t)blockIdx.x * blockDim.x + threadIdx.x;
    if (i >= n4) return;
    float4 v = src[i];
    __nv_bfloat16 hx = __float2bfloat16(v.x);
    __nv_bfloat16 hy = __float2bfloat16(v.y);
    __nv_bfloat16 hz = __float2bfloat16(v.z);
    __nv_bfloat16 hw = __float2bfloat16(v.w);
    __nv_bfloat16 lx = __float2bfloat16(v.x - __bfloat162float(hx));
    __nv_bfloat16 ly = __float2bfloat16(v.y - __bfloat162float(hy));
    __nv_bfloat16 lz = __float2bfloat16(v.z - __bfloat162float(hz));
    __nv_bfloat16 lw = __float2bfloat16(v.w - __bfloat162float(hw));
    uint2 ho, lu;
    ho.x = (uint32_t)__bfloat16_as_ushort(hx) | ((uint32_t)__bfloat16_as_ushort(hy) << 16);
    ho.y = (uint32_t)__bfloat16_as_ushort(hz) | ((uint32_t)__bfloat16_as_ushort(hw) << 16);
    lu.x = (uint32_t)__bfloat16_as_ushort(lx) | ((uint32_t)__bfloat16_as_ushort(ly) << 16);
    lu.y = (uint32_t)__bfloat16_as_ushort(lz) | ((uint32_t)__bfloat16_as_ushort(lw) << 16);
    hi[i] = ho;
    lo[i] = lu;
}

// ---------------- bf16-split mma GEMM (8 warps, 64x32 warp tile) --------------
#define KC    32
#define KCP   40
#define ARRB  (128*KCP*2)                // 10240
#define BUFB  (4*ARRB)                   // 40960

__global__ void __launch_bounds__(256, 2)
mma_gemm_kernel(const __nv_bfloat16* __restrict__ Ahi, const __nv_bfloat16* __restrict__ Alo,
                const __nv_bfloat16* __restrict__ Bhi, const __nv_bfloat16* __restrict__ Blo,
                const float* __restrict__ bias, float* __restrict__ C, int ldc)
{
    extern __shared__ __align__(16) char sm_raw[];

    const int tid  = threadIdx.x;
    const int lane = tid & 31;
    const int wid  = tid >> 5;
    const int wm   = wid >> 2;
    const int wn   = wid & 3;
    const int n0   = blockIdx.x * 128;
    const int m0   = blockIdx.y * 128;

    float acc[4][4][4];
#pragma unroll
    for (int i = 0; i < 4; ++i)
#pragma unroll
        for (int j = 0; j < 4; ++j)
#pragma unroll
            for (int v = 0; v < 4; ++v) acc[i][j][v] = 0.f;

    const int gr = tid >> 1;
    const int gs = (tid & 1) * 2;

    const uint32_t smBase = smem_u32(sm_raw);

    auto stage = [&](int c, int buf) {
        const int k0 = c * KC;
        uint32_t db = smBase + buf*BUFB + gr*(KCP*2) + gs*16;
        const __nv_bfloat16* pAh = Ahi + (size_t)(m0 + gr)*Hz + k0 + gs*8;
        const __nv_bfloat16* pAl = Alo + (size_t)(m0 + gr)*Hz + k0 + gs*8;
        const __nv_bfloat16* pBh = Bhi + (size_t)(n0 + gr)*Hz + k0 + gs*8;
        const __nv_bfloat16* pBl = Blo + (size_t)(n0 + gr)*Hz + k0 + gs*8;
#pragma unroll
        for (int i = 0; i < 2; ++i) {
            CP_ASYNC16_CG(db + i*16 + 0*ARRB, pAh + i*8);
            CP_ASYNC16_CG(db + i*16 + 1*ARRB, pAl + i*8);
            CP_ASYNC16_CG(db + i*16 + 2*ARRB, pBh + i*8);
            CP_ASYNC16_CG(db + i*16 + 3*ARRB, pBl + i*8);
        }
        CP_COMMIT();
    };

    const int NCHUNK = Hz / KC;   // 16
    stage(0, 0);

    for (int c = 0; c < NCHUNK; ++c) {
        if (c + 1 < NCHUNK) { stage(c + 1, (c + 1) & 1); CP_WAIT(1); }
        else                { CP_WAIT(0); }
        __syncthreads();

        const uint32_t bb  = smBase + (c & 1)*BUFB;
        const uint32_t uAh = bb;
        const uint32_t uAl = bb + 1*ARRB;
        const uint32_t uBh = bb + 2*ARRB;
        const uint32_t uBl = bb + 3*ARRB;

#pragma unroll
        for (int ks = 0; ks < KC/16; ++ks) {
            uint32_t fAh[4][4], fAl[4][4], fBh[4][2], fBl[4][2];
            const int arow = wm*64 + (lane & 15);
            const int acol = ks*16 + ((lane >> 4) << 3);
#pragma unroll
            for (int mt = 0; mt < 4; ++mt) {
                uint32_t off = ((arow + mt*16)*KCP + acol) * 2;
                ldsm4(fAh[mt], uAh + off);
                ldsm4(fAl[mt], uAl + off);
            }
            const int brow = wn*32 + (lane & 7) + ((lane >> 4) << 3);
            const int bcol = ks*16 + (lane & 8);
#pragma unroll
            for (int p = 0; p < 2; ++p) {
                uint32_t off = ((brow + p*16)*KCP + bcol) * 2;
                uint32_t t4[4];
                ldsm4(t4, uBh + off);
                fBh[2*p][0] = t4[0]; fBh[2*p][1] = t4[1];
                fBh[2*p+1][0] = t4[2]; fBh[2*p+1][1] = t4[3];
                ldsm4(t4, uBl + off);
                fBl[2*p][0] = t4[0]; fBl[2*p][1] = t4[1];
                fBl[2*p+1][0] = t4[2]; fBl[2*p+1][1] = t4[3];
            }
#pragma unroll
            for (int mt = 0; mt < 4; ++mt)
#pragma unroll
                for (int nt = 0; nt < 4; ++nt) mma_bf16(acc[mt][nt], fAh[mt], fBh[nt]);
#pragma unroll
            for (int mt = 0; mt < 4; ++mt)
#pragma unroll
                for (int nt = 0; nt < 4; ++nt) mma_bf16(acc[mt][nt], fAh[mt], fBl[nt]);
#pragma unroll
            for (int mt = 0; mt < 4; ++mt)
#pragma unroll
                for (int nt = 0; nt < 4; ++nt) mma_bf16(acc[mt][nt], fAl[mt], fBh[nt]);
        }
        __syncthreads();
    }

    const int gid = lane >> 2;
    const int tig = lane & 3;
#pragma unroll
    for (int mt = 0; mt < 4; ++mt) {
        int mA = m0 + wm*64 + mt*16 + gid;
#pragma unroll
        for (int nt = 0; nt < 4; ++nt) {
            int n = n0 + wn*32 + nt*8 + tig*2;
            float2 bv = *(const float2*)&bias[n];
            float2 v0 = make_float2(acc[mt][nt][0] + bv.x, acc[mt][nt][1] + bv.y);
            float2 v1 = make_float2(acc[mt][nt][2] + bv.x, acc[mt][nt][3] + bv.y);
            *(float2*)&C[(size_t)mA*ldc + n]     = v0;
            *(float2*)&C[(size_t)(mA+8)*ldc + n] = v1;
        }
    }
}

// ---------------- persistent scan: all weights register-resident -------------
#define SC_HB     0                          // 4 x 32768 staging
#define SC_SG     131072                     // 32768 partials
#define SC_ATTQ   (SC_SG + 32768)            // 2048
#define SC_SC     (SC_ATTQ + 2048)           // 512
#define SC_LSE    (SC_SC + 512)              // 16
#define SC_TOTAL  (SC_LSE + 16)

__global__ void __launch_bounds__(NTHR, 1)
scan_kernel(const float* __restrict__ ctx, const float* __restrict__ Whh,
            const float* __restrict__ Wih)
{
    extern __shared__ __align__(16) char dynsm[];
    float*  sgp    = (float*)(dynsm + SC_SG);
    float*  attq_s = (float*)(dynsm + SC_ATTQ);
    float*  sc_s   = (float*)(dynsm + SC_SC);
    float*  s_lse  = (float*)(dynsm + SC_LSE);
    const uint32_t smHb = smem_u32(dynsm);

    const int tid  = threadIdx.x;
    const int lane = tid & 31;
    const int w    = tid >> 5;
    const int wg   = w & 3;      // gate index (4 rows per warp)
    const int bh   = w >> 2;     // batch half
    const int blk  = blockIdx.x;
    const int j0   = blk * 4;
    const bool att_on = (blk & 1) == 0;
    const int cb   = blk >> 2;
    const int chalf = (blk >> 1) & 1;

    // ALL weight sets register-resident: layer0 Whh, layer1 Whh, layer1 Wih
    ulonglong2 wA[4][4], wBh[4][4], wBi[4][4];
#pragma unroll
    for (int jj = 0; jj < 4; ++jj) {
        const ulonglong2* W0 = (const ulonglong2*)(Whh + (size_t)(wg*Hz + j0 + jj)*Hz);
        const ulonglong2* W1 = (const ulonglong2*)(Whh + (size_t)(Gz + wg*Hz + j0 + jj)*Hz);
        const ulonglong2* W2 = (const ulonglong2*)(Wih + (size_t)(Gz + wg*Hz + j0 + jj)*Hz);
#pragma unroll
        for (int i = 0; i < 4; ++i) {
            wA[jj][i]  = W0[lane + 32*i];
            wBh[jj][i] = W1[lane + 32*i];
            wBi[jj][i] = W2[lane + 32*i];
        }
    }

    auto stageH = [&](const float4* src, int buf) {
        uint32_t db = smHb + buf*32768 + tid*16;
#pragma unroll
        for (int i = 0; i < 8; ++i)
            CP_ASYNC16_CG(db + i*NTHR*16, src + tid + i*NTHR);
        CP_COMMIT();
    };

    // gate GEMV: 4 rows x 16 batches from one staged buffer
    auto gates4 = [&](int buf, int boff, int slotbase, ulonglong2 (&wt)[4][4]) {
        const ulonglong2* hb2 = (const ulonglong2*)(dynsm + buf*32768);
#pragma unroll 2
        for (int bl = 0; bl < 16; ++bl) {
            ulonglong2 h2[4];
#pragma unroll
            for (int i = 0; i < 4; ++i) h2[i] = hb2[bl*128 + lane + 32*i];
            unsigned long long a0 = 0ull, a1 = 0ull, a2 = 0ull, a3 = 0ull;
#pragma unroll
            for (int i = 0; i < 4; ++i) {
                ffma2(a0, h2[i].x, wt[0][i].x); ffma2(a0, h2[i].y, wt[0][i].y);
                ffma2(a1, h2[i].x, wt[1][i].x); ffma2(a1, h2[i].y, wt[1][i].y);
                ffma2(a2, h2[i].x, wt[2][i].x); ffma2(a2, h2[i].y, wt[2][i].y);
                ffma2(a3, h2[i].x, wt[3][i].x); ffma2(a3, h2[i].y, wt[3][i].y);
            }
            float s[4];
            float2 f0 = unpack2(a0); s[0] = f0.x + f0.y;
            float2 f1 = unpack2(a1); s[1] = f1.x + f1.y;
            float2 f2 = unpack2(a2); s[2] = f2.x + f2.y;
            float2 f3 = unpack2(a3); s[3] = f3.x + f3.y;
#pragma unroll
            for (int jj = 0; jj < 4; ++jj) {
                s[jj] += __shfl_xor_sync(0xffffffffu, s[jj], 16);
                s[jj] += __shfl_xor_sync(0xffffffffu, s[jj], 8);
            }
            if (lane < 8) {
                int b = boff + bl;
#pragma unroll
                for (int jj = 0; jj < 4; ++jj)
                    sgp[((wg*4 + jj)*32 + b)*16 + slotbase + lane] = s[jj];
            }
        }
    };

    unsigned nbar = 0;

    // ---- prologue prefetch for t=0 ----
    {
        const float4* H0p = (const float4*)(d_h0buf);
        const float4* H1p = (const float4*)(d_h1buf);
        stageH(H0p, 0);        // group A1
        stageH(H0p + 2048, 1); // group A2
        stageH(H1p, 2);        // group Bh1
        stageH(H1p + 2048, 3); // group Bh2
    }

    for (int t = 0; t < Tz; ++t) {
        const int p = t & 1;
        float*       h0n = d_h0buf + (p^1)*Bz*Hz;
        float*       h1n = d_h1buf + (p^1)*Bz*Hz;

        // ===== Phase A: layer0 gates (h0 prefetched into bufs 0,1) =====
        {
            CP_WAIT(2);
            __syncthreads();
            if (bh == 0) gates4(0, 0,  0, wA);
            else         gates4(1, 16, 0, wA);
            __syncthreads();
            if (tid < 128) {
                int b = tid >> 2, jj = tid & 3;
                int j = j0 + jj;
                const float* seed = d_g0ih + ((size_t)t*Bz + b)*Gz;
                float g4[4];
#pragma unroll
                for (int g = 0; g < 4; ++g) {
                    const float4* q = (const float4*)&sgp[((g*4 + jj)*32 + b)*16];
                    float4 q0 = q[0], q1 = q[1];
                    g4[g] = (q0.x + q0.y) + (q0.z + q0.w) + (q1.x + q1.y) + (q1.z + q1.w);
                }
                float gi = g4[0] + seed[j];
                float gf = g4[1] + seed[Hz + j];
                float gg = g4[2] + seed[2*Hz + j];
                float go = g4[3] + seed[3*Hz + j];
                int ci = b*Hz + j;
                float c = sigf(gf)*d_cstate[ci] + sigf(gi)*tanhf(gg);
                float h = sigf(go)*tanhf(c);
                d_cstate[ci] = c;
                __stcg(&h0n[ci], h);
                __stcg(&d_cat1[ci], h + d_x[((size_t)t*Bz + b)*Hz + j]);
            }
        }
        gbar(nbar, blk);

        // ===== Phase B: pass1 h1 x Whh1 (bufs 2,3), pass2 cat1 x Wih1 =====
        {
            stageH((const float4*)d_cat1, 0);        // group Bc1
            stageH((const float4*)d_cat1 + 2048, 1); // group Bc2
            CP_WAIT(2);
            __syncthreads();
            if (bh == 0) gates4(2, 0,  8, wBh);      // h1 x Whh1 -> slots 8-15
            else         gates4(3, 16, 8, wBh);
            CP_WAIT(0);
            __syncthreads();
            if (bh == 0) gates4(0, 0,  0, wBi);      // cat1 x Wih1 -> slots 0-7
            else         gates4(1, 16, 0, wBi);
            __syncthreads();
            if (tid < 128) {
                int b = tid >> 2, jj = tid & 3;
                int j = j0 + jj;
                float g4[4];
#pragma unroll
                for (int g = 0; g < 4; ++g) {
                    const float4* q = (const float4*)&sgp[((g*4 + jj)*32 + b)*16];
                    float4 q0 = q[0], q1 = q[1], q2 = q[2], q3 = q[3];
                    g4[g] = ((q0.x + q0.y) + (q0.z + q0.w)) + ((q1.x + q1.y) + (q1.z + q1.w))
                          + ((q2.x + q2.y) + (q2.z + q2.w)) + ((q3.x + q3.y) + (q3.z + q3.w));
                }
                float gi = g4[0] + d_bias1[j];
                float gf = g4[1] + d_bias1[Hz + j];
                float gg = g4[2] + d_bias1[2*Hz + j];
                float go = g4[3] + d_bias1[3*Hz + j];
                int ci = Bz*Hz + b*Hz + j;
                float c = sigf(gf)*d_cstate[ci] + sigf(gi)*tanhf(gg);
                float h = sigf(go)*tanhf(c);
                d_cstate[ci] = c;
                __stcg(&h1n[b*Hz + j], h);
                __stcg(&d_attq[b*Hz + j], h + __ldcg(&d_cat1[b*Hz + j]));
            }
        }
        gbar(nbar, blk);

        // ===== prefetch next step's A (h0n) and B-h1 (h1n) =====
        if (t + 1 < Tz) {
            const float4* H0n = (const float4*)h0n;
            const float4* H1n = (const float4*)h1n;
            stageH(H0n, 0);
            stageH(H0n + 2048, 1);
            stageH(H1n, 2);
            stageH(H1n + 2048, 3);
        }

        // ===== Phase C: attention (even blocks; batch cb, H-half chalf) =====
        if (att_on) {
            for (int i = tid; i < Hz; i += NTHR) attq_s[i] = __ldcg(&d_attq[cb*Hz + i]);
            __syncthreads();

            const float4* A4 = (const float4*)attq_s;
            for (int s = w*16; s < w*16 + 16; ++s) {
                const float4* C4 = (const float4*)(ctx + ((size_t)cb*Sz + s)*Hz);
                float acc = 0.f;
#pragma unroll
                for (int i = 0; i < 4; ++i) {
                    float4 c4 = __ldcg(&C4[lane + 32*i]);
                    float4 a4 = A4[lane + 32*i];
                    acc += c4.x*a4.x + c4.y*a4.y + c4.z*a4.z + c4.w*a4.w;
                }
#pragma unroll
                for (int o = 16; o; o >>= 1) acc += __shfl_xor_sync(0xffffffffu, acc, o);
                if (lane == 0) sc_s[s] = acc;
            }
            __syncthreads();

            if (w == 0) {
                float m = -1e30f;
                for (int s = lane; s < Sz; s += 32) m = fmaxf(m, sc_s[s]);
#pragma unroll
                for (int o = 16; o; o >>= 1) m = fmaxf(m, __shfl_xor_sync(0xffffffffu, m, o));
                float sm = 0.f;
                for (int s = lane; s < Sz; s += 32) sm += expf(sc_s[s] - m);
#pragma unroll
                for (int o = 16; o; o >>= 1) sm += __shfl_xor_sync(0xffffffffu, sm, o);
                if (lane == 0) *s_lse = m + logf(sm);
            }
            __syncthreads();
            float lse = *s_lse;

            int h = chalf*256 + tid;
            const float* cp = ctx + (size_t)cb*Sz*Hz + h;
            float acc = 0.f;
#pragma unroll 8
            for (int s = 0; s < Sz; ++s)
                acc += __ldcg(&cp[(size_t)s*Hz]) * (sc_s[s] - lse);
            size_t oi = ((size_t)cb*Tz + t)*Hz + h;
            __nv_bfloat16 hv = __float2bfloat16(acc);
            d_out_hi[oi] = hv;
            d_out_lo[oi] = __float2bfloat16(acc - __bfloat162float(hv));
            __syncthreads();
        }
    }
}

// ---------------- tail: hT, cT ----------------
__global__ void tail_kernel(float* __restrict__ out)
{
    int i = blockIdx.x * blockDim.x + threadIdx.x;
    const size_t base = (size_t)Bz*Tz*Vz;
    if (i < Bz*Hz)                 out[base + i] = d_h0buf[i];
    else if (i < 2*Bz*Hz)          out[base + i] = d_h1buf[i - Bz*Hz];
    else if (i < 4*Bz*Hz)          out[base + i] = d_cstate[i - 2*Bz*Hz];
}

// ---------------- launch ----------------
extern "C" void kernel_launch(void* const* d_in, const int* in_sizes, int n_in,
                              void* d_out, int out_size)
{
    const float* context = (const float*)d_in[0];
    const int*   dec     = (const int*)d_in[1];
    const float* h0      = (const float*)d_in[2];
    const float* c0      = (const float*)d_in[3];
    const float* emb     = (const float*)d_in[4];
    const float* Wih     = (const float*)d_in[5];
    const float* Whh     = (const float*)d_in[6];
    const float* bih     = (const float*)d_in[7];
    const float* bhh     = (const float*)d_in[8];
    const float* Wc      = (const float*)d_in[9];
    const float* bc      = (const float*)d_in[10];
    float* out = (float*)d_out;

    float *p_g0ih, *p_b0;
    __nv_bfloat16 *p_wch, *p_wcl, *p_oh, *p_ol, *p_xh, *p_xl, *p_wih, *p_wil;
    cudaGetSymbolAddress((void**)&p_g0ih, d_g0ih);
    cudaGetSymbolAddress((void**)&p_b0,   d_bias0);
    cudaGetSymbolAddress((void**)&p_wch,  d_Wc_hi);
    cudaGetSymbolAddress((void**)&p_wcl,  d_Wc_lo);
    cudaGetSymbolAddress((void**)&p_oh,   d_out_hi);
    cudaGetSymbolAddress((void**)&p_ol,   d_out_lo);
    cudaGetSymbolAddress((void**)&p_xh,   d_x_hi);
    cudaGetSymbolAddress((void**)&p_xl,   d_x_lo);
    cudaGetSymbolAddress((void**)&p_wih,  d_Wih0_hi);
    cudaGetSymbolAddress((void**)&p_wil,  d_Wih0_lo);

    const int SMEM_MMA = 2 * BUFB;   // 81920 -> 2 CTAs/SM
    cudaFuncSetAttribute(mma_gemm_kernel,
                         cudaFuncAttributeMaxDynamicSharedMemorySize, SMEM_MMA);
    cudaFuncSetAttribute(scan_kernel,
                         cudaFuncAttributeMaxDynamicSharedMemorySize, SC_TOTAL);

    init_kernel<<<(Tz*Bz*Hz + 255)/256, 256>>>(dec, emb, bih, bhh, h0, c0);

    {
        size_t n4 = (size_t)Vz*Hz/4;
        split_kernel<<<(unsigned)((n4 + 255)/256), 256>>>((const float4*)Wc, (uint2*)p_wch, (uint2*)p_wcl, n4);
        size_t m4 = (size_t)Gz*Hz/4;
        split_kernel<<<(unsigned)((m4 + 255)/256), 256>>>((const float4*)Wih, (uint2*)p_wih, (uint2*)p_wil, m4);
    }

    // g0ih = x @ Wih0^T + bias0
    {
        dim3 grid(Gz/128, (Tz*Bz)/128);
        mma_gemm_kernel<<<grid, 256, SMEM_MMA>>>(p_xh, p_xl, p_wih, p_wil, p_b0, p_g0ih, Gz);
    }

    // persistent scan
    scan_kernel<<<NBLK, NTHR, SC_TOTAL>>>(context, Whh, Wih);

    // logits = outs @ Wc^T + bc
    {
        dim3 grid(Vz/128, (Bz*Tz)/128);
        mma_gemm_kernel<<<grid, 256, SMEM_MMA>>>(p_oh, p_ol, p_wch, p_wcl, bc, out, Vz);
    }

    if ((long long)out_size >= (long long)Bz*Tz*Vz + 4LL*Bz*Hz) {
        tail_kernel<<<(4*Bz*Hz + 255)/256, 256>>>(out);
    }
}